// round 1
// baseline (speedup 1.0000x reference)
#include <cuda_runtime.h>
#include <math.h>

#define BB   2
#define TT   2048
#define DD   1024
#define HH   16
#define DHH  64
#define MT   4096            // B*T
#define D3   3072            // 3*D
#define D4   4096            // 4*D

// ---------------- scratch (static device arrays; no allocation) ----------------
__device__ float g_h[MT * DD];                 // 16 MB  rmsnorm output
__device__ float g_qkv[(size_t)MT * D3];       // 48 MB  qkv projection
__device__ float g_att[MT * DD];               // 16 MB  attention output [b,t,h,dh]
__device__ float g_t1[(size_t)MT * D4];        // 64 MB  gate (then silu*up)
__device__ float g_t2[(size_t)MT * D4];        // 64 MB  up

// ---------------- RMSNorm: one block per row (D=1024, 256 thr * float4) -------
__global__ void rmsnorm_kernel(const float* __restrict__ x,
                               const float* __restrict__ w,
                               float* __restrict__ out) {
    int row = blockIdx.x;
    int t   = threadIdx.x;
    float4 xv = ((const float4*)(x + (size_t)row * DD))[t];
    float s = xv.x * xv.x + xv.y * xv.y + xv.z * xv.z + xv.w * xv.w;
#pragma unroll
    for (int o = 16; o; o >>= 1) s += __shfl_xor_sync(0xffffffffu, s, o);
    __shared__ float red[8];
    __shared__ float rs;
    if ((t & 31) == 0) red[t >> 5] = s;
    __syncthreads();
    if (t == 0) {
        float tot = 0.f;
#pragma unroll
        for (int i = 0; i < 8; i++) tot += red[i];
        rs = rsqrtf(tot * (1.0f / DD) + 1e-6f);
    }
    __syncthreads();
    float r = rs;
    float4 wv = ((const float4*)w)[t];
    float4 ov;
    ov.x = xv.x * r * wv.x;
    ov.y = xv.y * r * wv.y;
    ov.z = xv.z * r * wv.z;
    ov.w = xv.w * r * wv.w;
    ((float4*)(out + (size_t)row * DD))[t] = ov;
}

// ---------------- NT SGEMM: C[M,N] = A[M,K] @ B[N,K]^T (+res) ------------------
// 128x128 tile, BK=16, 256 threads, 8x8 micro-tile per thread.
// All problem dims divisible by tile sizes -> no bounds checks.
template <int ADDRES>
__global__ void __launch_bounds__(256)
gemm_nt(const float* __restrict__ A, const float* __restrict__ B,
        float* __restrict__ C, const float* __restrict__ R,
        int M, int N, int K) {
    __shared__ float As[16][128];
    __shared__ float Bs[16][128];
    int tid = threadIdx.x;
    int bm = blockIdx.y * 128, bn = blockIdx.x * 128;
    int lr = tid >> 2;            // 0..63
    int lk = (tid & 3) << 2;      // 0,4,8,12
    const float* Ag = A + (size_t)(bm + lr) * K + lk;
    const float* Bg = B + (size_t)(bn + lr) * K + lk;
    int tr = (tid >> 4) << 3;     // 0..120
    int tc = (tid & 15) << 3;     // 0..120
    float acc[8][8];
#pragma unroll
    for (int i = 0; i < 8; i++)
#pragma unroll
        for (int j = 0; j < 8; j++) acc[i][j] = 0.f;

    for (int k0 = 0; k0 < K; k0 += 16) {
        float4 a0 = *(const float4*)Ag;
        float4 a1 = *(const float4*)(Ag + (size_t)64 * K);
        float4 b0 = *(const float4*)Bg;
        float4 b1 = *(const float4*)(Bg + (size_t)64 * K);
        __syncthreads();
        As[lk + 0][lr] = a0.x; As[lk + 1][lr] = a0.y; As[lk + 2][lr] = a0.z; As[lk + 3][lr] = a0.w;
        As[lk + 0][lr + 64] = a1.x; As[lk + 1][lr + 64] = a1.y; As[lk + 2][lr + 64] = a1.z; As[lk + 3][lr + 64] = a1.w;
        Bs[lk + 0][lr] = b0.x; Bs[lk + 1][lr] = b0.y; Bs[lk + 2][lr] = b0.z; Bs[lk + 3][lr] = b0.w;
        Bs[lk + 0][lr + 64] = b1.x; Bs[lk + 1][lr + 64] = b1.y; Bs[lk + 2][lr + 64] = b1.z; Bs[lk + 3][lr + 64] = b1.w;
        __syncthreads();
        Ag += 16; Bg += 16;
#pragma unroll
        for (int kk = 0; kk < 16; kk++) {
            float ar[8], br[8];
            *(float4*)&ar[0] = *(const float4*)&As[kk][tr];
            *(float4*)&ar[4] = *(const float4*)&As[kk][tr + 4];
            *(float4*)&br[0] = *(const float4*)&Bs[kk][tc];
            *(float4*)&br[4] = *(const float4*)&Bs[kk][tc + 4];
#pragma unroll
            for (int i = 0; i < 8; i++)
#pragma unroll
                for (int j = 0; j < 8; j++) acc[i][j] += ar[i] * br[j];
        }
    }
#pragma unroll
    for (int i = 0; i < 8; i++) {
        size_t off = (size_t)(bm + tr + i) * N + bn + tc;
#pragma unroll
        for (int j = 0; j < 8; j += 4) {
            float4 v = make_float4(acc[i][j], acc[i][j + 1], acc[i][j + 2], acc[i][j + 3]);
            if (ADDRES) {
                float4 r4 = *(const float4*)(R + off + j);
                v.x += r4.x; v.y += r4.y; v.z += r4.z; v.w += r4.w;
            }
            *(float4*)(C + off + j) = v;
        }
    }
}

// ---------------- split qkv -> k_cache / v_cache ([b,h,t,dh]) ------------------
__global__ void split_kv_kernel(const float* __restrict__ qkv,
                                float* __restrict__ kc, float* __restrict__ vc) {
    int idx = blockIdx.x * 256 + threadIdx.x;     // one float4 each
    int e = idx << 2;                             // element index in [b,h,t,dh]
    int dh = e & 63;
    int t  = (e >> 6) & 2047;
    int h  = (e >> 17) & 15;
    int b  = e >> 21;
    const float* src = qkv + (size_t)(b * TT + t) * D3 + DD + h * DHH + dh;
    *(float4*)(kc + e) = *(const float4*)src;
    *(float4*)(vc + e) = *(const float4*)(src + DD);
}

// ---------------- flash attention, causal, 64-query tiles ----------------------
// 256 threads: thread = (row = tid>>2 in 0..63, colblock cb = (tid&3)*16).
// q row kept in registers (16 float4). Online softmax state replicated per quad.
__global__ void __launch_bounds__(256)
attn_kernel(const float* __restrict__ qkv, const float* __restrict__ kc,
            const float* __restrict__ vc, float* __restrict__ out) {
    extern __shared__ float sm[];
    float* sk = sm;                 // [64][68]
    float* sv = sm + 64 * 68;       // [64][68]
    float* ss = sm + 2 * 64 * 68;   // [64][68]  p tile
    int qt = blockIdx.x;            // 0..31
    int bh = blockIdx.y;            // 0..31
    int b = bh >> 4, h = bh & 15;
    int tid = threadIdx.x;
    int row = tid >> 2;
    int cb  = (tid & 3) << 4;

    // q row -> registers, pre-scaled by 1/sqrt(Dh)
    float4 q[16];
    const float* qg = qkv + (size_t)(b * TT + qt * 64 + row) * D3 + h * DHH;
#pragma unroll
    for (int i = 0; i < 16; i++) {
        float4 v = *(const float4*)(qg + 4 * i);
        v.x *= 0.125f; v.y *= 0.125f; v.z *= 0.125f; v.w *= 0.125f;
        q[i] = v;
    }

    float o[16];
#pragma unroll
    for (int j = 0; j < 16; j++) o[j] = 0.f;
    float mx = -1e30f, l = 0.f;

    const float* kg0 = kc + (size_t)bh * TT * DHH;
    const float* vg0 = vc + (size_t)bh * TT * DHH;

    for (int jt = 0; jt <= qt; jt++) {
        __syncthreads();   // prior p@v done before overwriting sk/sv
        {
            const float* kg = kg0 + (size_t)(jt * 64 + row) * DHH + cb;
            const float* vg = vg0 + (size_t)(jt * 64 + row) * DHH + cb;
#pragma unroll
            for (int j = 0; j < 16; j += 4) {
                *(float4*)&sk[row * 68 + cb + j] = *(const float4*)(kg + j);
                *(float4*)&sv[row * 68 + cb + j] = *(const float4*)(vg + j);
            }
        }
        __syncthreads();

        bool diag = (jt == qt);
        float pvv[16];
        float tm = -1e30f;
#pragma unroll
        for (int j = 0; j < 16; j++) {
            const float* kr = sk + (cb + j) * 68;
            float a0 = 0, a1 = 0, a2 = 0, a3 = 0;
#pragma unroll
            for (int k = 0; k < 16; k++) {
                float4 kv = *(const float4*)(kr + 4 * k);
                a0 += q[k].x * kv.x; a1 += q[k].y * kv.y;
                a2 += q[k].z * kv.z; a3 += q[k].w * kv.w;
            }
            float a = (a0 + a1) + (a2 + a3);
            if (diag && (cb + j) > row) a = -1e30f;
            pvv[j] = a;
            tm = fmaxf(tm, a);
        }
        tm = fmaxf(tm, __shfl_xor_sync(0xffffffffu, tm, 1));
        tm = fmaxf(tm, __shfl_xor_sync(0xffffffffu, tm, 2));
        float mn = fmaxf(mx, tm);
        float corr = __expf(mx - mn);
        mx = mn;
        float rsum = 0.f;
#pragma unroll
        for (int j = 0; j < 16; j++) {
            float p = __expf(pvv[j] - mn);
            rsum += p;
            ss[row * 68 + cb + j] = p;
        }
        rsum += __shfl_xor_sync(0xffffffffu, rsum, 1);
        rsum += __shfl_xor_sync(0xffffffffu, rsum, 2);
        l = l * corr + rsum;
#pragma unroll
        for (int j = 0; j < 16; j++) o[j] *= corr;
        __syncwarp();      // quad-local p writes visible before p@v reads

#pragma unroll 4
        for (int k = 0; k < 64; k++) {
            float p = ss[row * 68 + k];
            const float* vr = sv + k * 68 + cb;
#pragma unroll
            for (int j = 0; j < 16; j += 4) {
                float4 vv = *(const float4*)(vr + j);
                o[j]     += p * vv.x;
                o[j + 1] += p * vv.y;
                o[j + 2] += p * vv.z;
                o[j + 3] += p * vv.w;
            }
        }
    }

    float inv = 1.f / l;
    float* og = g_att ? out + (size_t)(b * TT + qt * 64 + row) * DD + h * DHH + cb
                      : out;   // (branch always true; keeps out generic)
#pragma unroll
    for (int j = 0; j < 16; j += 4) {
        float4 v = make_float4(o[j] * inv, o[j + 1] * inv, o[j + 2] * inv, o[j + 3] * inv);
        *(float4*)(og + j) = v;
    }
}

// ---------------- silu(gate) * up, in-place into gate --------------------------
__global__ void silu_mul_kernel(float* __restrict__ g, const float* __restrict__ u) {
    int idx = blockIdx.x * 256 + threadIdx.x;
    float4 a = ((const float4*)g)[idx];
    float4 bV = ((const float4*)u)[idx];
    a.x = a.x / (1.f + __expf(-a.x)) * bV.x;
    a.y = a.y / (1.f + __expf(-a.y)) * bV.y;
    a.z = a.z / (1.f + __expf(-a.z)) * bV.z;
    a.w = a.w / (1.f + __expf(-a.w)) * bV.w;
    ((float4*)g)[idx] = a;
}

// ---------------- launch ------------------------------------------------------
extern "C" void kernel_launch(void* const* d_in, const int* in_sizes, int n_in,
                              void* d_out, int out_size) {
    const float* x       = (const float*)d_in[0];
    const float* w_norm1 = (const float*)d_in[1];
    const float* w_qkv   = (const float*)d_in[2];
    const float* w_proj  = (const float*)d_in[3];
    const float* w_norm2 = (const float*)d_in[4];
    const float* w_gate  = (const float*)d_in[5];
    const float* w_up    = (const float*)d_in[6];
    const float* w_down  = (const float*)d_in[7];
    // d_in[8] = step (unused in prefill path)

    float* xo = (float*)d_out;                           // x out: [B,T,D]
    float* kc = xo + (size_t)MT * DD;                    // k_cache: [B,H,T,Dh]
    float* vc = kc + (size_t)BB * HH * TT * DHH;         // v_cache

    float *h, *qkv, *att, *t1, *t2;
    cudaGetSymbolAddress((void**)&h,   g_h);
    cudaGetSymbolAddress((void**)&qkv, g_qkv);
    cudaGetSymbolAddress((void**)&att, g_att);
    cudaGetSymbolAddress((void**)&t1,  g_t1);
    cudaGetSymbolAddress((void**)&t2,  g_t2);

    // 1. h = rmsnorm(x) * w1
    rmsnorm_kernel<<<MT, 256>>>(x, w_norm1, h);
    // 2. qkv = h @ w_qkv^T
    gemm_nt<0><<<dim3(D3 / 128, MT / 128), 256>>>(h, w_qkv, qkv, nullptr, MT, D3, DD);
    // 3. scatter k/v into caches (also final outputs)
    split_kv_kernel<<<(BB * HH * TT * DHH / 4) / 256, 256>>>(qkv, kc, vc);
    // 4. causal flash attention -> att [b,t,h,dh]
    int smem = 3 * 64 * 68 * (int)sizeof(float);
    cudaFuncSetAttribute(attn_kernel, cudaFuncAttributeMaxDynamicSharedMemorySize, smem);
    attn_kernel<<<dim3(TT / 64, BB * HH), 256, smem>>>(qkv, kc, vc, att);
    // 5. x = x + att @ w_proj^T
    gemm_nt<1><<<dim3(DD / 128, MT / 128), 256>>>(att, w_proj, xo, x, MT, DD, DD);
    // 6. h = rmsnorm(x) * w2
    rmsnorm_kernel<<<MT, 256>>>(xo, w_norm2, h);
    // 7. gate / up
    gemm_nt<0><<<dim3(D4 / 128, MT / 128), 256>>>(h, w_gate, t1, nullptr, MT, D4, DD);
    gemm_nt<0><<<dim3(D4 / 128, MT / 128), 256>>>(h, w_up,   t2, nullptr, MT, D4, DD);
    // 8. t1 = silu(t1) * t2
    silu_mul_kernel<<<((size_t)MT * D4 / 4) / 256, 256>>>(t1, t2);
    // 9. x += t1 @ w_down^T
    gemm_nt<1><<<dim3(DD / 128, MT / 128), 256>>>(t1, w_down, xo, xo, MT, DD, D4);
}

// round 2
// speedup vs baseline: 1.4294x; 1.4294x over previous
#include <cuda_runtime.h>
#include <math.h>
#include <stdint.h>

#define BB   2
#define TT   2048
#define DD   1024
#define HH   16
#define DHH  64
#define MT   4096            // B*T
#define D3   3072            // 3*D
#define D4   4096            // 4*D

// ---------------- scratch (static device arrays; no allocation) ----------------
__device__ float g_h[MT * DD];                 // 16 MB  rmsnorm output
__device__ float g_qkv[(size_t)MT * D3];       // 48 MB  qkv projection
__device__ float g_att[MT * DD];               // 16 MB  attention output [b,t,h,dh]
__device__ float g_t1[(size_t)MT * D4];        // 64 MB  gate (then silu*up)
__device__ float g_t2[(size_t)MT * D4];        // 64 MB  up

// ---------------- RMSNorm: one block per row (D=1024, 256 thr * float4) -------
__global__ void rmsnorm_kernel(const float* __restrict__ x,
                               const float* __restrict__ w,
                               float* __restrict__ out) {
    int row = blockIdx.x;
    int t   = threadIdx.x;
    float4 xv = ((const float4*)(x + (size_t)row * DD))[t];
    float s = xv.x * xv.x + xv.y * xv.y + xv.z * xv.z + xv.w * xv.w;
#pragma unroll
    for (int o = 16; o; o >>= 1) s += __shfl_xor_sync(0xffffffffu, s, o);
    __shared__ float red[8];
    __shared__ float rs;
    if ((t & 31) == 0) red[t >> 5] = s;
    __syncthreads();
    if (t == 0) {
        float tot = 0.f;
#pragma unroll
        for (int i = 0; i < 8; i++) tot += red[i];
        rs = rsqrtf(tot * (1.0f / DD) + 1e-6f);
    }
    __syncthreads();
    float r = rs;
    float4 wv = ((const float4*)w)[t];
    float4 ov;
    ov.x = xv.x * r * wv.x;
    ov.y = xv.y * r * wv.y;
    ov.z = xv.z * r * wv.z;
    ov.w = xv.w * r * wv.w;
    ((float4*)(out + (size_t)row * DD))[t] = ov;
}

// ---------------- tf32 helpers -------------------------------------------------
__device__ __forceinline__ float tf32r(float x) {
    uint32_t u;
    asm("cvt.rna.tf32.f32 %0, %1;" : "=r"(u) : "f"(x));
    return __uint_as_float(u);
}
__device__ __forceinline__ float4 tf32r4(float4 v) {
    v.x = tf32r(v.x); v.y = tf32r(v.y); v.z = tf32r(v.z); v.w = tf32r(v.w);
    return v;
}

__device__ __forceinline__ void mma_tf32(float* c, const uint32_t* a, const uint32_t* b) {
    asm volatile(
        "mma.sync.aligned.m16n8k8.row.col.f32.tf32.tf32.f32 "
        "{%0,%1,%2,%3}, {%4,%5,%6,%7}, {%8,%9}, {%0,%1,%2,%3};\n"
        : "+f"(c[0]), "+f"(c[1]), "+f"(c[2]), "+f"(c[3])
        : "r"(a[0]), "r"(a[1]), "r"(a[2]), "r"(a[3]), "r"(b[0]), "r"(b[1]));
}

// ---------------- tf32 tensor-core NT GEMM: C[M,N] = A[M,K] @ B[N,K]^T (+res) --
// Block 128x128, BK=16, 256 threads = 8 warps (2M x 4N), warp tile 64x32.
// smem m-major [row][20] (pad 4): conflict-free fragment LDS, aligned float4 STS.
#define SAST 20
template <int ADDRES>
__global__ void __launch_bounds__(256)
gemm_tf32(const float* __restrict__ A, const float* __restrict__ B,
          float* __restrict__ C, const float* __restrict__ R,
          int M, int N, int K) {
    __shared__ float As[2][128][SAST];
    __shared__ float Bs[2][128][SAST];
    int tid  = threadIdx.x;
    int warp = tid >> 5, lane = tid & 31;
    int g = lane >> 2, tig = lane & 3;
    int wm = (warp >> 2) * 64;     // 0 or 64
    int wn = (warp & 3) * 32;      // 0,32,64,96
    int bm = blockIdx.y * 128, bn = blockIdx.x * 128;

    // global load mapping: row = lr (+64), k-chunk = lk..lk+3
    int lr = tid >> 2;             // 0..63
    int lk = (tid & 3) << 2;       // 0,4,8,12
    const float* Ag = A + (size_t)(bm + lr) * K + lk;
    const float* Bg = B + (size_t)(bn + lr) * K + lk;

    float acc[4][4][4];
#pragma unroll
    for (int i = 0; i < 4; i++)
#pragma unroll
        for (int j = 0; j < 4; j++)
#pragma unroll
            for (int q = 0; q < 4; q++) acc[i][j][q] = 0.f;

    // prologue: tile 0 -> regs -> smem[0]
    float4 pa0 = tf32r4(*(const float4*)Ag);
    float4 pa1 = tf32r4(*(const float4*)(Ag + (size_t)64 * K));
    float4 pb0 = tf32r4(*(const float4*)Bg);
    float4 pb1 = tf32r4(*(const float4*)(Bg + (size_t)64 * K));
    *(float4*)&As[0][lr][lk]      = pa0;
    *(float4*)&As[0][lr + 64][lk] = pa1;
    *(float4*)&Bs[0][lr][lk]      = pb0;
    *(float4*)&Bs[0][lr + 64][lk] = pb1;
    __syncthreads();

    int buf = 0;
    for (int k0 = 0;;) {
        int nxt = k0 + 16;
        if (nxt < K) {
            const float* Agn = Ag + nxt;
            const float* Bgn = Bg + nxt;
            pa0 = tf32r4(*(const float4*)Agn);
            pa1 = tf32r4(*(const float4*)(Agn + (size_t)64 * K));
            pb0 = tf32r4(*(const float4*)Bgn);
            pb1 = tf32r4(*(const float4*)(Bgn + (size_t)64 * K));
        }
        // compute 2 k-steps of 8 from smem[buf]
#pragma unroll
        for (int ks = 0; ks < 2; ks++) {
            const int kk = ks * 8;
            uint32_t af[4][4], bf[4][2];
#pragma unroll
            for (int mt = 0; mt < 4; mt++) {
                int m = wm + mt * 16 + g;
                af[mt][0] = __float_as_uint(As[buf][m][kk + tig]);
                af[mt][1] = __float_as_uint(As[buf][m + 8][kk + tig]);
                af[mt][2] = __float_as_uint(As[buf][m][kk + tig + 4]);
                af[mt][3] = __float_as_uint(As[buf][m + 8][kk + tig + 4]);
            }
#pragma unroll
            for (int nt = 0; nt < 4; nt++) {
                int n = wn + nt * 8 + g;
                bf[nt][0] = __float_as_uint(Bs[buf][n][kk + tig]);
                bf[nt][1] = __float_as_uint(Bs[buf][n][kk + tig + 4]);
            }
#pragma unroll
            for (int mt = 0; mt < 4; mt++)
#pragma unroll
                for (int nt = 0; nt < 4; nt++)
                    mma_tf32(acc[mt][nt], af[mt], bf[nt]);
        }
        if (nxt >= K) break;
        __syncthreads();
        int nb = buf ^ 1;
        *(float4*)&As[nb][lr][lk]      = pa0;
        *(float4*)&As[nb][lr + 64][lk] = pa1;
        *(float4*)&Bs[nb][lr][lk]      = pb0;
        *(float4*)&Bs[nb][lr + 64][lk] = pb1;
        __syncthreads();
        buf = nb;
        k0 = nxt;
    }

    // epilogue
#pragma unroll
    for (int mt = 0; mt < 4; mt++) {
#pragma unroll
        for (int nt = 0; nt < 4; nt++) {
            int r0 = bm + wm + mt * 16 + g;
            int c0 = bn + wn + nt * 8 + 2 * tig;
            size_t o0 = (size_t)r0 * N + c0;
            size_t o1 = (size_t)(r0 + 8) * N + c0;
            float2 v0 = make_float2(acc[mt][nt][0], acc[mt][nt][1]);
            float2 v1 = make_float2(acc[mt][nt][2], acc[mt][nt][3]);
            if (ADDRES) {
                float2 r4 = *(const float2*)(R + o0);
                v0.x += r4.x; v0.y += r4.y;
                float2 r5 = *(const float2*)(R + o1);
                v1.x += r5.x; v1.y += r5.y;
            }
            *(float2*)(C + o0) = v0;
            *(float2*)(C + o1) = v1;
        }
    }
}

// ---------------- split qkv -> k_cache / v_cache ([b,h,t,dh]) ------------------
__global__ void split_kv_kernel(const float* __restrict__ qkv,
                                float* __restrict__ kc, float* __restrict__ vc) {
    int idx = blockIdx.x * 256 + threadIdx.x;     // one float4 each
    int e = idx << 2;                             // element index in [b,h,t,dh]
    int dh = e & 63;
    int t  = (e >> 6) & 2047;
    int h  = (e >> 17) & 15;
    int b  = e >> 21;
    const float* src = qkv + (size_t)(b * TT + t) * D3 + DD + h * DHH + dh;
    *(float4*)(kc + e) = *(const float4*)src;
    *(float4*)(vc + e) = *(const float4*)(src + DD);
}

// ---------------- flash attention, causal, 64-query tiles ----------------------
__global__ void __launch_bounds__(256)
attn_kernel(const float* __restrict__ qkv, const float* __restrict__ kc,
            const float* __restrict__ vc, float* __restrict__ out) {
    extern __shared__ float sm[];
    float* sk = sm;                 // [64][68]
    float* sv = sm + 64 * 68;       // [64][68]
    float* ss = sm + 2 * 64 * 68;   // [64][68]  p tile
    int qt = blockIdx.x;            // 0..31
    int bh = blockIdx.y;            // 0..31
    int b = bh >> 4, h = bh & 15;
    int tid = threadIdx.x;
    int row = tid >> 2;
    int cb  = (tid & 3) << 4;

    float4 q[16];
    const float* qg = qkv + (size_t)(b * TT + qt * 64 + row) * D3 + h * DHH;
#pragma unroll
    for (int i = 0; i < 16; i++) {
        float4 v = *(const float4*)(qg + 4 * i);
        v.x *= 0.125f; v.y *= 0.125f; v.z *= 0.125f; v.w *= 0.125f;
        q[i] = v;
    }

    float o[16];
#pragma unroll
    for (int j = 0; j < 16; j++) o[j] = 0.f;
    float mx = -1e30f, l = 0.f;

    const float* kg0 = kc + (size_t)bh * TT * DHH;
    const float* vg0 = vc + (size_t)bh * TT * DHH;

    for (int jt = 0; jt <= qt; jt++) {
        __syncthreads();
        {
            const float* kg = kg0 + (size_t)(jt * 64 + row) * DHH + cb;
            const float* vg = vg0 + (size_t)(jt * 64 + row) * DHH + cb;
#pragma unroll
            for (int j = 0; j < 16; j += 4) {
                *(float4*)&sk[row * 68 + cb + j] = *(const float4*)(kg + j);
                *(float4*)&sv[row * 68 + cb + j] = *(const float4*)(vg + j);
            }
        }
        __syncthreads();

        bool diag = (jt == qt);
        float pvv[16];
        float tm = -1e30f;
#pragma unroll
        for (int j = 0; j < 16; j++) {
            const float* kr = sk + (cb + j) * 68;
            float a0 = 0, a1 = 0, a2 = 0, a3 = 0;
#pragma unroll
            for (int k = 0; k < 16; k++) {
                float4 kv = *(const float4*)(kr + 4 * k);
                a0 += q[k].x * kv.x; a1 += q[k].y * kv.y;
                a2 += q[k].z * kv.z; a3 += q[k].w * kv.w;
            }
            float a = (a0 + a1) + (a2 + a3);
            if (diag && (cb + j) > row) a = -1e30f;
            pvv[j] = a;
            tm = fmaxf(tm, a);
        }
        tm = fmaxf(tm, __shfl_xor_sync(0xffffffffu, tm, 1));
        tm = fmaxf(tm, __shfl_xor_sync(0xffffffffu, tm, 2));
        float mn = fmaxf(mx, tm);
        float corr = __expf(mx - mn);
        mx = mn;
        float rsum = 0.f;
#pragma unroll
        for (int j = 0; j < 16; j++) {
            float p = __expf(pvv[j] - mn);
            rsum += p;
            ss[row * 68 + cb + j] = p;
        }
        rsum += __shfl_xor_sync(0xffffffffu, rsum, 1);
        rsum += __shfl_xor_sync(0xffffffffu, rsum, 2);
        l = l * corr + rsum;
#pragma unroll
        for (int j = 0; j < 16; j++) o[j] *= corr;
        __syncwarp();

#pragma unroll 4
        for (int k = 0; k < 64; k++) {
            float p = ss[row * 68 + k];
            const float* vr = sv + k * 68 + cb;
#pragma unroll
            for (int j = 0; j < 16; j += 4) {
                float4 vv = *(const float4*)(vr + j);
                o[j]     += p * vv.x;
                o[j + 1] += p * vv.y;
                o[j + 2] += p * vv.z;
                o[j + 3] += p * vv.w;
            }
        }
    }

    float inv = 1.f / l;
    float* og = out + (size_t)(b * TT + qt * 64 + row) * DD + h * DHH + cb;
#pragma unroll
    for (int j = 0; j < 16; j += 4) {
        float4 v = make_float4(o[j] * inv, o[j + 1] * inv, o[j + 2] * inv, o[j + 3] * inv);
        *(float4*)(og + j) = v;
    }
}

// ---------------- silu(gate) * up, in-place into gate --------------------------
__global__ void silu_mul_kernel(float* __restrict__ g, const float* __restrict__ u) {
    int idx = blockIdx.x * 256 + threadIdx.x;
    float4 a = ((const float4*)g)[idx];
    float4 bV = ((const float4*)u)[idx];
    a.x = a.x / (1.f + __expf(-a.x)) * bV.x;
    a.y = a.y / (1.f + __expf(-a.y)) * bV.y;
    a.z = a.z / (1.f + __expf(-a.z)) * bV.z;
    a.w = a.w / (1.f + __expf(-a.w)) * bV.w;
    ((float4*)g)[idx] = a;
}

// ---------------- launch ------------------------------------------------------
extern "C" void kernel_launch(void* const* d_in, const int* in_sizes, int n_in,
                              void* d_out, int out_size) {
    const float* x       = (const float*)d_in[0];
    const float* w_norm1 = (const float*)d_in[1];
    const float* w_qkv   = (const float*)d_in[2];
    const float* w_proj  = (const float*)d_in[3];
    const float* w_norm2 = (const float*)d_in[4];
    const float* w_gate  = (const float*)d_in[5];
    const float* w_up    = (const float*)d_in[6];
    const float* w_down  = (const float*)d_in[7];

    float* xo = (float*)d_out;                           // x out: [B,T,D]
    float* kc = xo + (size_t)MT * DD;                    // k_cache: [B,H,T,Dh]
    float* vc = kc + (size_t)BB * HH * TT * DHH;         // v_cache

    float *h, *qkv, *att, *t1, *t2;
    cudaGetSymbolAddress((void**)&h,   g_h);
    cudaGetSymbolAddress((void**)&qkv, g_qkv);
    cudaGetSymbolAddress((void**)&att, g_att);
    cudaGetSymbolAddress((void**)&t1,  g_t1);
    cudaGetSymbolAddress((void**)&t2,  g_t2);

    // 1. h = rmsnorm(x) * w1
    rmsnorm_kernel<<<MT, 256>>>(x, w_norm1, h);
    // 2. qkv = h @ w_qkv^T
    gemm_tf32<0><<<dim3(D3 / 128, MT / 128), 256>>>(h, w_qkv, qkv, nullptr, MT, D3, DD);
    // 3. scatter k/v into caches (also final outputs)
    split_kv_kernel<<<(BB * HH * TT * DHH / 4) / 256, 256>>>(qkv, kc, vc);
    // 4. causal flash attention -> att [b,t,h,dh]
    int smem = 3 * 64 * 68 * (int)sizeof(float);
    cudaFuncSetAttribute(attn_kernel, cudaFuncAttributeMaxDynamicSharedMemorySize, smem);
    attn_kernel<<<dim3(TT / 64, BB * HH), 256, smem>>>(qkv, kc, vc, att);
    // 5. x = x + att @ w_proj^T
    gemm_tf32<1><<<dim3(DD / 128, MT / 128), 256>>>(att, w_proj, xo, x, MT, DD, DD);
    // 6. h = rmsnorm(x) * w2
    rmsnorm_kernel<<<MT, 256>>>(xo, w_norm2, h);
    // 7. gate / up
    gemm_tf32<0><<<dim3(D4 / 128, MT / 128), 256>>>(h, w_gate, t1, nullptr, MT, D4, DD);
    gemm_tf32<0><<<dim3(D4 / 128, MT / 128), 256>>>(h, w_up,   t2, nullptr, MT, D4, DD);
    // 8. t1 = silu(t1) * t2
    silu_mul_kernel<<<((size_t)MT * D4 / 4) / 256, 256>>>(t1, t2);
    // 9. x += t1 @ w_down^T
    gemm_tf32<1><<<dim3(DD / 128, MT / 128), 256>>>(t1, w_down, xo, xo, MT, DD, D4);
}

// round 3
// speedup vs baseline: 1.6135x; 1.1288x over previous
#include <cuda_runtime.h>
#include <math.h>
#include <stdint.h>

#define BB   2
#define TT   2048
#define DD   1024
#define HH   16
#define DHH  64
#define MT   4096            // B*T
#define D3   3072            // 3*D
#define D4   4096            // 4*D
#define D8   8192            // gate+up stacked

// ---------------- scratch (static device arrays; no allocation) ----------------
__device__ float g_h[MT * DD];                  // 16 MB  rmsnorm output (tf32)
__device__ float g_qkv[(size_t)MT * D3];        // 48 MB  qkv projection (fp32)
__device__ float g_att[MT * DD];                // 16 MB  attention out (tf32)
__device__ float g_gu[(size_t)MT * D8];         // 128 MB gate|up combined
__device__ float g_t1[(size_t)MT * D4];         // 64 MB  silu(gate)*up (tf32)
__device__ float g_wc[16 * 1024 * 1024];        // 64 MB  converted weights (tf32)
// g_wc layout: [0,3M) w_qkv | [3M,4M) w_proj | [4M,12M) w_gate;w_up | [12M,16M) w_down

// ---------------- tf32 helpers -------------------------------------------------
__device__ __forceinline__ float tf32r(float x) {
    uint32_t u;
    asm("cvt.rna.tf32.f32 %0, %1;" : "=r"(u) : "f"(x));
    return __uint_as_float(u);
}
__device__ __forceinline__ float4 tf32r4(float4 v) {
    v.x = tf32r(v.x); v.y = tf32r(v.y); v.z = tf32r(v.z); v.w = tf32r(v.w);
    return v;
}

__device__ __forceinline__ void mma_tf32(float* c, const uint32_t* a, const uint32_t* b) {
    asm volatile(
        "mma.sync.aligned.m16n8k8.row.col.f32.tf32.tf32.f32 "
        "{%0,%1,%2,%3}, {%4,%5,%6,%7}, {%8,%9}, {%0,%1,%2,%3};\n"
        : "+f"(c[0]), "+f"(c[1]), "+f"(c[2]), "+f"(c[3])
        : "r"(a[0]), "r"(a[1]), "r"(a[2]), "r"(a[3]), "r"(b[0]), "r"(b[1]));
}
__device__ __forceinline__ void ldsm4(uint32_t* r, uint32_t addr) {
    asm volatile("ldmatrix.sync.aligned.m8n8.x4.shared.b16 {%0,%1,%2,%3}, [%4];"
                 : "=r"(r[0]), "=r"(r[1]), "=r"(r[2]), "=r"(r[3]) : "r"(addr));
}
__device__ __forceinline__ void cpa16(uint32_t dst, const void* src) {
    asm volatile("cp.async.cg.shared.global [%0], [%1], 16;" :: "r"(dst), "l"(src));
}
__device__ __forceinline__ void cp_commit() {
    asm volatile("cp.async.commit_group;");
}
template <int N>
__device__ __forceinline__ void cp_wait() {
    asm volatile("cp.async.wait_group %0;" :: "n"(N));
}

// ---------------- weight convert: fp32 -> tf32 ---------------------------------
__global__ void cvt_kernel(const float* __restrict__ src, float* __restrict__ dst, int n4) {
    int idx = blockIdx.x * 256 + threadIdx.x;
    if (idx < n4) ((float4*)dst)[idx] = tf32r4(((const float4*)src)[idx]);
}

// ---------------- RMSNorm (tf32-rounded output) --------------------------------
__global__ void rmsnorm_kernel(const float* __restrict__ x,
                               const float* __restrict__ w,
                               float* __restrict__ out) {
    int row = blockIdx.x;
    int t   = threadIdx.x;
    float4 xv = ((const float4*)(x + (size_t)row * DD))[t];
    float s = xv.x * xv.x + xv.y * xv.y + xv.z * xv.z + xv.w * xv.w;
#pragma unroll
    for (int o = 16; o; o >>= 1) s += __shfl_xor_sync(0xffffffffu, s, o);
    __shared__ float red[8];
    __shared__ float rs;
    if ((t & 31) == 0) red[t >> 5] = s;
    __syncthreads();
    if (t == 0) {
        float tot = 0.f;
#pragma unroll
        for (int i = 0; i < 8; i++) tot += red[i];
        rs = rsqrtf(tot * (1.0f / DD) + 1e-6f);
    }
    __syncthreads();
    float r = rs;
    float4 wv = ((const float4*)w)[t];
    float4 ov;
    ov.x = xv.x * r * wv.x;
    ov.y = xv.y * r * wv.y;
    ov.z = xv.z * r * wv.z;
    ov.w = xv.w * r * wv.w;
    ((float4*)(out + (size_t)row * DD))[t] = tf32r4(ov);
}

// ---------------- tf32 tensor-core NT GEMM (cp.async + ldmatrix) ---------------
// C[M,N] = A[M,K] @ B[N,K]^T (+R). A,B must already be tf32-rounded.
// Block 128x128, BK=16, 4-stage cp.async pipeline, 256 threads = 8 warps (2Mx4N).
#define SAST 20
#define STG  4
#define GEMM_SMEM (STG * 128 * SAST * 2 * 4)

template <int ADDRES>
__global__ void __launch_bounds__(256, 2)
gemm_tc(const float* __restrict__ A, const float* __restrict__ B,
        float* __restrict__ C, const float* __restrict__ R,
        int M, int N, int K) {
    extern __shared__ float smf[];
    const int AS = 128 * SAST;                 // floats per stage (one matrix)
    uint32_t sA = (uint32_t)__cvta_generic_to_shared(smf);
    uint32_t sB = sA + STG * AS * 4;

    int tid  = threadIdx.x;
    int warp = tid >> 5, lane = tid & 31;
    int g = lane >> 2, tig = lane & 3;
    int wm = (warp >> 2) * 64;
    int wn = (warp & 3) * 32;
    int bm = blockIdx.y * 128, bn = blockIdx.x * 128;

    int lr = tid >> 2;             // 0..63
    int lk = (tid & 3) << 2;       // 0,4,8,12
    const float* Ag = A + (size_t)(bm + lr) * K + lk;
    const float* Bg = B + (size_t)(bn + lr) * K + lk;

    // cp.async dst offsets (bytes), per stage add stage*AS*4
    uint32_t dA0 = sA + (uint32_t)(lr * SAST + lk) * 4;
    uint32_t dA1 = sA + (uint32_t)((lr + 64) * SAST + lk) * 4;
    uint32_t dB0 = sB + (uint32_t)(lr * SAST + lk) * 4;
    uint32_t dB1 = sB + (uint32_t)((lr + 64) * SAST + lk) * 4;

    // ldmatrix address components
    int aRow = wm + (lane & 15);
    int aCol = ((lane >> 4) & 1) * 4;
    int bRow = wn + (lane & 7) + ((lane >> 4) & 1) * 8;
    int bCol = ((lane >> 3) & 1) * 4;

    float acc[4][4][4];
#pragma unroll
    for (int i = 0; i < 4; i++)
#pragma unroll
        for (int j = 0; j < 4; j++)
#pragma unroll
            for (int q = 0; q < 4; q++) acc[i][j][q] = 0.f;

    // prologue: issue stages 0..STG-2
#pragma unroll
    for (int s = 0; s < STG - 1; s++) {
        uint32_t so = (uint32_t)(s * AS * 4);
        int ko = s * 16;
        cpa16(dA0 + so, Ag + ko);
        cpa16(dA1 + so, Ag + (size_t)64 * K + ko);
        cpa16(dB0 + so, Bg + ko);
        cpa16(dB1 + so, Bg + (size_t)64 * K + ko);
        cp_commit();
    }

    int rd = 0, wr = STG - 1;
    int iters = K >> 4;
    cp_wait<STG - 2>();
    __syncthreads();

    for (int it = 0; it < iters; it++) {
        // compute stage rd: 2 k-steps of 8
        uint32_t stA = sA + (uint32_t)(rd * AS * 4);
        uint32_t stB = sB + (uint32_t)(rd * AS * 4);
#pragma unroll
        for (int ks = 0; ks < 2; ks++) {
            int kk = ks * 8;
            uint32_t af[4][4], bf[2][4];
#pragma unroll
            for (int mt = 0; mt < 4; mt++)
                ldsm4(af[mt], stA + (uint32_t)((aRow + mt * 16) * SAST + kk + aCol) * 4);
#pragma unroll
            for (int np = 0; np < 2; np++)
                ldsm4(bf[np], stB + (uint32_t)((bRow + np * 16) * SAST + kk + bCol) * 4);
#pragma unroll
            for (int mt = 0; mt < 4; mt++)
#pragma unroll
                for (int nt = 0; nt < 4; nt++)
                    mma_tf32(acc[mt][nt], af[mt], &bf[nt >> 1][(nt & 1) * 2]);
        }
        // prefetch next tile into stage wr
        int nk = (it + STG - 1) * 16;
        if (nk < K) {
            uint32_t so = (uint32_t)(wr * AS * 4);
            cpa16(dA0 + so, Ag + nk);
            cpa16(dA1 + so, Ag + (size_t)64 * K + nk);
            cpa16(dB0 + so, Bg + nk);
            cpa16(dB1 + so, Bg + (size_t)64 * K + nk);
        }
        cp_commit();
        wr = rd;
        rd = (rd + 1) & (STG - 1);
        cp_wait<STG - 2>();
        __syncthreads();
    }

    // epilogue
#pragma unroll
    for (int mt = 0; mt < 4; mt++) {
#pragma unroll
        for (int nt = 0; nt < 4; nt++) {
            int r0 = bm + wm + mt * 16 + g;
            int c0 = bn + wn + nt * 8 + 2 * tig;
            size_t o0 = (size_t)r0 * N + c0;
            size_t o1 = (size_t)(r0 + 8) * N + c0;
            float2 v0 = make_float2(acc[mt][nt][0], acc[mt][nt][1]);
            float2 v1 = make_float2(acc[mt][nt][2], acc[mt][nt][3]);
            if (ADDRES) {
                float2 r4 = *(const float2*)(R + o0);
                v0.x += r4.x; v0.y += r4.y;
                float2 r5 = *(const float2*)(R + o1);
                v1.x += r5.x; v1.y += r5.y;
            }
            *(float2*)(C + o0) = v0;
            *(float2*)(C + o1) = v1;
        }
    }
}

// ---------------- split qkv -> k_cache / v_cache ([b,h,t,dh]) ------------------
__global__ void split_kv_kernel(const float* __restrict__ qkv,
                                float* __restrict__ kc, float* __restrict__ vc) {
    int idx = blockIdx.x * 256 + threadIdx.x;     // one float4 each
    int e = idx << 2;                             // element index in [b,h,t,dh]
    int dh = e & 63;
    int t  = (e >> 6) & 2047;
    int h  = (e >> 17) & 15;
    int b  = e >> 21;
    const float* src = qkv + (size_t)(b * TT + t) * D3 + DD + h * DHH + dh;
    *(float4*)(kc + e) = *(const float4*)src;
    *(float4*)(vc + e) = *(const float4*)(src + DD);
}

// ---------------- flash attention, causal, 64-query tiles ----------------------
__global__ void __launch_bounds__(256)
attn_kernel(const float* __restrict__ qkv, const float* __restrict__ kc,
            const float* __restrict__ vc, float* __restrict__ out) {
    extern __shared__ float sm[];
    float* sk = sm;                 // [64][68]
    float* sv = sm + 64 * 68;       // [64][68]
    float* ss = sm + 2 * 64 * 68;   // [64][68]  p tile
    int qt = blockIdx.x;            // 0..31
    int bh = blockIdx.y;            // 0..31
    int b = bh >> 4, h = bh & 15;
    int tid = threadIdx.x;
    int row = tid >> 2;
    int cb  = (tid & 3) << 4;

    float4 q[16];
    const float* qg = qkv + (size_t)(b * TT + qt * 64 + row) * D3 + h * DHH;
#pragma unroll
    for (int i = 0; i < 16; i++) {
        float4 v = *(const float4*)(qg + 4 * i);
        v.x *= 0.125f; v.y *= 0.125f; v.z *= 0.125f; v.w *= 0.125f;
        q[i] = v;
    }

    float o[16];
#pragma unroll
    for (int j = 0; j < 16; j++) o[j] = 0.f;
    float mx = -1e30f, l = 0.f;

    const float* kg0 = kc + (size_t)bh * TT * DHH;
    const float* vg0 = vc + (size_t)bh * TT * DHH;

    for (int jt = 0; jt <= qt; jt++) {
        __syncthreads();
        {
            const float* kg = kg0 + (size_t)(jt * 64 + row) * DHH + cb;
            const float* vg = vg0 + (size_t)(jt * 64 + row) * DHH + cb;
#pragma unroll
            for (int j = 0; j < 16; j += 4) {
                *(float4*)&sk[row * 68 + cb + j] = *(const float4*)(kg + j);
                *(float4*)&sv[row * 68 + cb + j] = *(const float4*)(vg + j);
            }
        }
        __syncthreads();

        bool diag = (jt == qt);
        float pvv[16];
        float tm = -1e30f;
#pragma unroll
        for (int j = 0; j < 16; j++) {
            const float* kr = sk + (cb + j) * 68;
            float a0 = 0, a1 = 0, a2 = 0, a3 = 0;
#pragma unroll
            for (int k = 0; k < 16; k++) {
                float4 kv = *(const float4*)(kr + 4 * k);
                a0 += q[k].x * kv.x; a1 += q[k].y * kv.y;
                a2 += q[k].z * kv.z; a3 += q[k].w * kv.w;
            }
            float a = (a0 + a1) + (a2 + a3);
            if (diag && (cb + j) > row) a = -1e30f;
            pvv[j] = a;
            tm = fmaxf(tm, a);
        }
        tm = fmaxf(tm, __shfl_xor_sync(0xffffffffu, tm, 1));
        tm = fmaxf(tm, __shfl_xor_sync(0xffffffffu, tm, 2));
        float mn = fmaxf(mx, tm);
        float corr = __expf(mx - mn);
        mx = mn;
        float rsum = 0.f;
#pragma unroll
        for (int j = 0; j < 16; j++) {
            float p = __expf(pvv[j] - mn);
            rsum += p;
            ss[row * 68 + cb + j] = p;
        }
        rsum += __shfl_xor_sync(0xffffffffu, rsum, 1);
        rsum += __shfl_xor_sync(0xffffffffu, rsum, 2);
        l = l * corr + rsum;
#pragma unroll
        for (int j = 0; j < 16; j++) o[j] *= corr;
        __syncwarp();

#pragma unroll 4
        for (int k = 0; k < 64; k++) {
            float p = ss[row * 68 + k];
            const float* vr = sv + k * 68 + cb;
#pragma unroll
            for (int j = 0; j < 16; j += 4) {
                float4 vv = *(const float4*)(vr + j);
                o[j]     += p * vv.x;
                o[j + 1] += p * vv.y;
                o[j + 2] += p * vv.z;
                o[j + 3] += p * vv.w;
            }
        }
    }

    float inv = 1.f / l;
    float* og = out + (size_t)(b * TT + qt * 64 + row) * DD + h * DHH + cb;
#pragma unroll
    for (int j = 0; j < 16; j += 4) {
        float4 v = make_float4(o[j] * inv, o[j + 1] * inv, o[j + 2] * inv, o[j + 3] * inv);
        *(float4*)(og + j) = tf32r4(v);   // tf32 for proj GEMM cp.async path
    }
}

// ---------------- silu(gate) * up from combined [M,8192] -> t1 [M,4096] tf32 ---
__global__ void silu_mul_kernel(const float* __restrict__ gu, float* __restrict__ t1) {
    int idx = blockIdx.x * 256 + threadIdx.x;     // float4 index into t1
    int m  = idx >> 10;                           // 1024 float4 per row
    int j4 = idx & 1023;
    const float4* rowp = (const float4*)(gu + (size_t)m * D8);
    float4 a = rowp[j4];
    float4 bV = rowp[j4 + 1024];
    a.x = a.x / (1.f + __expf(-a.x)) * bV.x;
    a.y = a.y / (1.f + __expf(-a.y)) * bV.y;
    a.z = a.z / (1.f + __expf(-a.z)) * bV.z;
    a.w = a.w / (1.f + __expf(-a.w)) * bV.w;
    ((float4*)t1)[idx] = tf32r4(a);
}

// ---------------- launch ------------------------------------------------------
extern "C" void kernel_launch(void* const* d_in, const int* in_sizes, int n_in,
                              void* d_out, int out_size) {
    const float* x       = (const float*)d_in[0];
    const float* w_norm1 = (const float*)d_in[1];
    const float* w_qkv   = (const float*)d_in[2];
    const float* w_proj  = (const float*)d_in[3];
    const float* w_norm2 = (const float*)d_in[4];
    const float* w_gate  = (const float*)d_in[5];
    const float* w_up    = (const float*)d_in[6];
    const float* w_down  = (const float*)d_in[7];

    float* xo = (float*)d_out;                           // x out: [B,T,D]
    float* kc = xo + (size_t)MT * DD;                    // k_cache: [B,H,T,Dh]
    float* vc = kc + (size_t)BB * HH * TT * DHH;         // v_cache

    float *h, *qkv, *att, *gu, *t1, *wc;
    cudaGetSymbolAddress((void**)&h,   g_h);
    cudaGetSymbolAddress((void**)&qkv, g_qkv);
    cudaGetSymbolAddress((void**)&att, g_att);
    cudaGetSymbolAddress((void**)&gu,  g_gu);
    cudaGetSymbolAddress((void**)&t1,  g_t1);
    cudaGetSymbolAddress((void**)&wc,  g_wc);

    float* wc_qkv  = wc;
    float* wc_proj = wc + (size_t)3 * 1024 * 1024;
    float* wc_gu   = wc + (size_t)4 * 1024 * 1024;
    float* wc_up   = wc_gu + (size_t)4 * 1024 * 1024;
    float* wc_down = wc + (size_t)12 * 1024 * 1024;

    cudaFuncSetAttribute(gemm_tc<0>, cudaFuncAttributeMaxDynamicSharedMemorySize, GEMM_SMEM);
    cudaFuncSetAttribute(gemm_tc<1>, cudaFuncAttributeMaxDynamicSharedMemorySize, GEMM_SMEM);

    // 0. convert weights to tf32 (gate/up stacked into one [8192,1024] matrix)
    cvt_kernel<<<(3 * 1024 * 1024 / 4) / 256, 256>>>(w_qkv,  wc_qkv,  3 * 1024 * 1024 / 4);
    cvt_kernel<<<(1024 * 1024 / 4) / 256,     256>>>(w_proj, wc_proj, 1024 * 1024 / 4);
    cvt_kernel<<<(4 * 1024 * 1024 / 4) / 256, 256>>>(w_gate, wc_gu,   4 * 1024 * 1024 / 4);
    cvt_kernel<<<(4 * 1024 * 1024 / 4) / 256, 256>>>(w_up,   wc_up,   4 * 1024 * 1024 / 4);
    cvt_kernel<<<(4 * 1024 * 1024 / 4) / 256, 256>>>(w_down, wc_down, 4 * 1024 * 1024 / 4);

    // 1. h = tf32(rmsnorm(x) * w1)
    rmsnorm_kernel<<<MT, 256>>>(x, w_norm1, h);
    // 2. qkv = h @ w_qkv^T
    gemm_tc<0><<<dim3(D3 / 128, MT / 128), 256, GEMM_SMEM>>>(h, wc_qkv, qkv, nullptr, MT, D3, DD);
    // 3. scatter k/v into caches (also final outputs)
    split_kv_kernel<<<(BB * HH * TT * DHH / 4) / 256, 256>>>(qkv, kc, vc);
    // 4. causal flash attention -> att [b,t,h,dh] (tf32-rounded)
    int smem = 3 * 64 * 68 * (int)sizeof(float);
    cudaFuncSetAttribute(attn_kernel, cudaFuncAttributeMaxDynamicSharedMemorySize, smem);
    attn_kernel<<<dim3(TT / 64, BB * HH), 256, smem>>>(qkv, kc, vc, att);
    // 5. x = x + att @ w_proj^T
    gemm_tc<1><<<dim3(DD / 128, MT / 128), 256, GEMM_SMEM>>>(att, wc_proj, xo, x, MT, DD, DD);
    // 6. h = tf32(rmsnorm(x) * w2)
    rmsnorm_kernel<<<MT, 256>>>(xo, w_norm2, h);
    // 7. gate|up combined: gu = h @ [w_gate;w_up]^T   (N=8192)
    gemm_tc<0><<<dim3(D8 / 128, MT / 128), 256, GEMM_SMEM>>>(h, wc_gu, gu, nullptr, MT, D8, DD);
    // 8. t1 = tf32(silu(gate) * up)
    silu_mul_kernel<<<((size_t)MT * D4 / 4) / 256, 256>>>(gu, t1);
    // 9. x += t1 @ w_down^T
    gemm_tc<1><<<dim3(DD / 128, MT / 128), 256, GEMM_SMEM>>>(t1, wc_down, xo, xo, MT, DD, D4);
}

// round 4
// speedup vs baseline: 6.4540x; 4.0001x over previous
#include <cuda_runtime.h>
#include <math.h>
#include <stdint.h>

#define BB   2
#define TT   2048
#define DD   1024
#define HH   16
#define DHH  64
#define MT   4096            // B*T
#define D3   3072            // 3*D
#define D4   4096            // 4*D
#define D8   8192            // gate+up stacked

// ---------------- scratch (static device arrays; no allocation) ----------------
__device__ float g_h[MT * DD];                  // rmsnorm output (tf32)
__device__ float g_qkv[(size_t)MT * D3];        // qkv projection (fp32)
__device__ float g_att[MT * DD];                // attention out (tf32)
__device__ float g_gu[(size_t)MT * D8];         // gate|up combined
__device__ float g_t1[(size_t)MT * D4];         // silu(gate)*up (tf32)
__device__ float g_wc[16 * 1024 * 1024];        // converted weights (tf32)
__device__ float g_kt[(size_t)BB * HH * TT * DHH];  // tf32 K  [bh][t][dh]
__device__ float g_vt[(size_t)BB * HH * TT * DHH];  // tf32 V^T [bh][dh][t]

// ---------------- tf32 / mma helpers -------------------------------------------
__device__ __forceinline__ float tf32r(float x) {
    uint32_t u;
    asm("cvt.rna.tf32.f32 %0, %1;" : "=r"(u) : "f"(x));
    return __uint_as_float(u);
}
__device__ __forceinline__ float4 tf32r4(float4 v) {
    v.x = tf32r(v.x); v.y = tf32r(v.y); v.z = tf32r(v.z); v.w = tf32r(v.w);
    return v;
}
__device__ __forceinline__ void mma_tf32(float* c, const uint32_t* a, const uint32_t* b) {
    asm volatile(
        "mma.sync.aligned.m16n8k8.row.col.f32.tf32.tf32.f32 "
        "{%0,%1,%2,%3}, {%4,%5,%6,%7}, {%8,%9}, {%0,%1,%2,%3};\n"
        : "+f"(c[0]), "+f"(c[1]), "+f"(c[2]), "+f"(c[3])
        : "r"(a[0]), "r"(a[1]), "r"(a[2]), "r"(a[3]), "r"(b[0]), "r"(b[1]));
}
__device__ __forceinline__ void ldsm4(uint32_t* r, uint32_t addr) {
    asm volatile("ldmatrix.sync.aligned.m8n8.x4.shared.b16 {%0,%1,%2,%3}, [%4];"
                 : "=r"(r[0]), "=r"(r[1]), "=r"(r[2]), "=r"(r[3]) : "r"(addr));
}
__device__ __forceinline__ void cpa16(uint32_t dst, const void* src) {
    asm volatile("cp.async.cg.shared.global [%0], [%1], 16;" :: "r"(dst), "l"(src));
}
__device__ __forceinline__ void cp_commit() {
    asm volatile("cp.async.commit_group;");
}
template <int N>
__device__ __forceinline__ void cp_wait() {
    asm volatile("cp.async.wait_group %0;" :: "n"(N));
}

// ---------------- weight convert: fp32 -> tf32 ---------------------------------
__global__ void cvt_kernel(const float* __restrict__ src, float* __restrict__ dst, int n4) {
    int idx = blockIdx.x * 256 + threadIdx.x;
    if (idx < n4) ((float4*)dst)[idx] = tf32r4(((const float4*)src)[idx]);
}

// ---------------- RMSNorm (tf32-rounded output) --------------------------------
__global__ void rmsnorm_kernel(const float* __restrict__ x,
                               const float* __restrict__ w,
                               float* __restrict__ out) {
    int row = blockIdx.x;
    int t   = threadIdx.x;
    float4 xv = ((const float4*)(x + (size_t)row * DD))[t];
    float s = xv.x * xv.x + xv.y * xv.y + xv.z * xv.z + xv.w * xv.w;
#pragma unroll
    for (int o = 16; o; o >>= 1) s += __shfl_xor_sync(0xffffffffu, s, o);
    __shared__ float red[8];
    __shared__ float rs;
    if ((t & 31) == 0) red[t >> 5] = s;
    __syncthreads();
    if (t == 0) {
        float tot = 0.f;
#pragma unroll
        for (int i = 0; i < 8; i++) tot += red[i];
        rs = rsqrtf(tot * (1.0f / DD) + 1e-6f);
    }
    __syncthreads();
    float r = rs;
    float4 wv = ((const float4*)w)[t];
    float4 ov;
    ov.x = xv.x * r * wv.x;
    ov.y = xv.y * r * wv.y;
    ov.z = xv.z * r * wv.z;
    ov.w = xv.w * r * wv.w;
    ((float4*)(out + (size_t)row * DD))[t] = tf32r4(ov);
}

// ---------------- tf32 tensor-core NT GEMM (cp.async + ldmatrix) ---------------
#define SAST 20
#define STG  4
#define GEMM_SMEM (STG * 128 * SAST * 2 * 4)

template <int ADDRES>
__global__ void __launch_bounds__(256, 2)
gemm_tc(const float* __restrict__ A, const float* __restrict__ B,
        float* __restrict__ C, const float* __restrict__ R,
        int M, int N, int K) {
    extern __shared__ float smf[];
    const int AS = 128 * SAST;
    uint32_t sA = (uint32_t)__cvta_generic_to_shared(smf);
    uint32_t sB = sA + STG * AS * 4;

    int tid  = threadIdx.x;
    int warp = tid >> 5, lane = tid & 31;
    int g = lane >> 2, tig = lane & 3;
    int wm = (warp >> 2) * 64;
    int wn = (warp & 3) * 32;
    int bm = blockIdx.y * 128, bn = blockIdx.x * 128;

    int lr = tid >> 2;
    int lk = (tid & 3) << 2;
    const float* Ag = A + (size_t)(bm + lr) * K + lk;
    const float* Bg = B + (size_t)(bn + lr) * K + lk;

    uint32_t dA0 = sA + (uint32_t)(lr * SAST + lk) * 4;
    uint32_t dA1 = sA + (uint32_t)((lr + 64) * SAST + lk) * 4;
    uint32_t dB0 = sB + (uint32_t)(lr * SAST + lk) * 4;
    uint32_t dB1 = sB + (uint32_t)((lr + 64) * SAST + lk) * 4;

    int aRow = wm + (lane & 15);
    int aCol = ((lane >> 4) & 1) * 4;
    int bRow = wn + (lane & 7) + ((lane >> 4) & 1) * 8;
    int bCol = ((lane >> 3) & 1) * 4;

    float acc[4][4][4];
#pragma unroll
    for (int i = 0; i < 4; i++)
#pragma unroll
        for (int j = 0; j < 4; j++)
#pragma unroll
            for (int q = 0; q < 4; q++) acc[i][j][q] = 0.f;

#pragma unroll
    for (int s = 0; s < STG - 1; s++) {
        uint32_t so = (uint32_t)(s * AS * 4);
        int ko = s * 16;
        cpa16(dA0 + so, Ag + ko);
        cpa16(dA1 + so, Ag + (size_t)64 * K + ko);
        cpa16(dB0 + so, Bg + ko);
        cpa16(dB1 + so, Bg + (size_t)64 * K + ko);
        cp_commit();
    }

    int rd = 0, wr = STG - 1;
    int iters = K >> 4;
    cp_wait<STG - 2>();
    __syncthreads();

    for (int it = 0; it < iters; it++) {
        uint32_t stA = sA + (uint32_t)(rd * AS * 4);
        uint32_t stB = sB + (uint32_t)(rd * AS * 4);
#pragma unroll
        for (int ks = 0; ks < 2; ks++) {
            int kk = ks * 8;
            uint32_t af[4][4], bf[2][4];
#pragma unroll
            for (int mt = 0; mt < 4; mt++)
                ldsm4(af[mt], stA + (uint32_t)((aRow + mt * 16) * SAST + kk + aCol) * 4);
#pragma unroll
            for (int np = 0; np < 2; np++)
                ldsm4(bf[np], stB + (uint32_t)((bRow + np * 16) * SAST + kk + bCol) * 4);
#pragma unroll
            for (int mt = 0; mt < 4; mt++)
#pragma unroll
                for (int nt = 0; nt < 4; nt++)
                    mma_tf32(acc[mt][nt], af[mt], &bf[nt >> 1][(nt & 1) * 2]);
        }
        int nk = (it + STG - 1) * 16;
        if (nk < K) {
            uint32_t so = (uint32_t)(wr * AS * 4);
            cpa16(dA0 + so, Ag + nk);
            cpa16(dA1 + so, Ag + (size_t)64 * K + nk);
            cpa16(dB0 + so, Bg + nk);
            cpa16(dB1 + so, Bg + (size_t)64 * K + nk);
        }
        cp_commit();
        wr = rd;
        rd = (rd + 1) & (STG - 1);
        cp_wait<STG - 2>();
        __syncthreads();
    }

#pragma unroll
    for (int mt = 0; mt < 4; mt++) {
#pragma unroll
        for (int nt = 0; nt < 4; nt++) {
            int r0 = bm + wm + mt * 16 + g;
            int c0 = bn + wn + nt * 8 + 2 * tig;
            size_t o0 = (size_t)r0 * N + c0;
            size_t o1 = (size_t)(r0 + 8) * N + c0;
            float2 v0 = make_float2(acc[mt][nt][0], acc[mt][nt][1]);
            float2 v1 = make_float2(acc[mt][nt][2], acc[mt][nt][3]);
            if (ADDRES) {
                float2 r4 = *(const float2*)(R + o0);
                v0.x += r4.x; v0.y += r4.y;
                float2 r5 = *(const float2*)(R + o1);
                v1.x += r5.x; v1.y += r5.y;
            }
            *(float2*)(C + o0) = v0;
            *(float2*)(C + o1) = v1;
        }
    }
}

// ---------------- split qkv -> kc/vc (exact) + kt (tf32) + vt (tf32, transposed)
__global__ void split_kv_kernel(const float* __restrict__ qkv,
                                float* __restrict__ kc, float* __restrict__ vc,
                                float* __restrict__ kt, float* __restrict__ vt) {
    int idx = blockIdx.x * 256 + threadIdx.x;     // one float4 each
    int e = idx << 2;                             // element index in [b,h,t,dh]
    int dh = e & 63;
    int t  = (e >> 6) & 2047;
    int h  = (e >> 17) & 15;
    int b  = e >> 21;
    const float* src = qkv + (size_t)(b * TT + t) * D3 + DD + h * DHH + dh;
    float4 k4 = *(const float4*)src;
    float4 v4 = *(const float4*)(src + DD);
    *(float4*)(kc + e) = k4;
    *(float4*)(vc + e) = v4;
    *(float4*)(kt + e) = tf32r4(k4);
    float4 vr = tf32r4(v4);
    float* vb = vt + ((size_t)(b * HH + h) * DHH + dh) * TT + t;
    vb[0] = vr.x; vb[TT] = vr.y; vb[2 * TT] = vr.z; vb[3 * TT] = vr.w;
}

// ---------------- tensor-core flash attention ----------------------------------
// Q-tile 128, KV-tile 64, 8 warps; warp w owns S rows wm..wm+15 (all 64 kv cols).
// smem: sK[2][64][68] | sV[2][64][68] | sP[128][68] (Q staging, then P per warp).
#define ASTR 68
#define KVF  (64 * ASTR)                 // floats per K/V stage
#define ATT_SMEM ((2 * KVF + 2 * KVF + 128 * ASTR) * 4)
#define NEGINF __int_as_float(0xff800000)

__global__ void __launch_bounds__(256, 2)
attn_mma(const float* __restrict__ qkv, const float* __restrict__ kt,
         const float* __restrict__ vt, float* __restrict__ out) {
    extern __shared__ float smf[];
    uint32_t sbase = (uint32_t)__cvta_generic_to_shared(smf);
    const uint32_t sK = sbase;
    const uint32_t sV = sbase + 2 * KVF * 4;
    const uint32_t sP = sbase + 4 * KVF * 4;
    float* pmem = smf + 4 * KVF;

    int qt = (int)(gridDim.x - 1) - (int)blockIdx.x;   // big tiles first
    int bh = blockIdx.y;
    int b = bh >> 4, h = bh & 15;
    int q0 = qt * 128;
    int tid = threadIdx.x;
    int warp = tid >> 5, lane = tid & 31;
    int g = lane >> 2, tig = lane & 3;
    int wm = warp * 16;

    const float* ktb = kt + (size_t)bh * TT * DHH;     // [t][dh]
    const float* vtb = vt + (size_t)bh * DHH * TT;     // [dh][t]

    // ---- stage Q tile into sP (tf32, pre-scaled), extract warp A-frags --------
    {
        int row = tid >> 1;
        int c0 = (tid & 1) * 32;
        const float* src = qkv + ((size_t)(b * TT + q0 + row)) * D3 + h * DHH + c0;
        float* dst = pmem + row * ASTR + c0;
#pragma unroll
        for (int j = 0; j < 8; j++) {
            float4 v = *(const float4*)(src + 4 * j);
            v.x *= 0.125f; v.y *= 0.125f; v.z *= 0.125f; v.w *= 0.125f;
            *(float4*)(dst + 4 * j) = tf32r4(v);
        }
    }
    __syncthreads();
    uint32_t qf[8][4];
    {
        int aRow = wm + (lane & 15);
        int aCol = (lane >> 4) * 4;
#pragma unroll
        for (int kk = 0; kk < 8; kk++)
            ldsm4(qf[kk], sP + (uint32_t)(aRow * ASTR + kk * 8 + aCol) * 4);
    }
    __syncthreads();    // sP now free for P tiles

    float o[8][4];
#pragma unroll
    for (int nt = 0; nt < 8; nt++)
#pragma unroll
        for (int i = 0; i < 4; i++) o[nt][i] = 0.f;
    float mx0 = -1e30f, mx1 = -1e30f, l0 = 0.f, l1 = 0.f;

    int nT = 2 * qt + 2;
    int bRow = (lane & 7) + ((lane >> 4) & 1) * 8;
    int bCol4 = ((lane >> 3) & 1) * 4;
    int aRowP = wm + (lane & 15);
    int aColP = (lane >> 4) * 4;

    // tile loader: K rows = kv tokens, V rows = dh
    auto load_tile = [&](int jt, int s) {
        int kv = jt * 64;
        int r = tid >> 2;
        int cb = (tid & 3) * 16;
        const float* ksrc = ktb + (size_t)(kv + r) * DHH + cb;
        const float* vsrc = vtb + (size_t)r * TT + kv + cb;
        uint32_t kd = sK + (uint32_t)(s * KVF + r * ASTR + cb) * 4;
        uint32_t vd = sV + (uint32_t)(s * KVF + r * ASTR + cb) * 4;
#pragma unroll
        for (int i = 0; i < 4; i++) {
            cpa16(kd + i * 16, ksrc + i * 4);
            cpa16(vd + i * 16, vsrc + i * 4);
        }
    };

    load_tile(0, 0);
    cp_commit();

    for (int jt = 0; jt < nT; jt++) {
        int buf = jt & 1;
        if (jt + 1 < nT) { load_tile(jt + 1, buf ^ 1); cp_commit(); cp_wait<1>(); }
        else             { cp_commit(); cp_wait<0>(); }
        __syncthreads();

        int kv0 = jt * 64;
        if (kv0 <= q0 + wm + 15) {      // not fully masked for this warp
            // ---- S = Q @ K^T
            float acc[8][4];
#pragma unroll
            for (int nt = 0; nt < 8; nt++)
#pragma unroll
                for (int i = 0; i < 4; i++) acc[nt][i] = 0.f;
            uint32_t kbase = sK + (uint32_t)(buf * KVF) * 4;
#pragma unroll
            for (int kk = 0; kk < 8; kk++) {
                uint32_t bf[4][4];
#pragma unroll
                for (int np = 0; np < 4; np++)
                    ldsm4(bf[np], kbase + (uint32_t)((np * 16 + bRow) * ASTR + kk * 8 + bCol4) * 4);
#pragma unroll
                for (int nt = 0; nt < 8; nt++)
                    mma_tf32(acc[nt], qf[kk], &bf[nt >> 1][(nt & 1) * 2]);
            }

            // ---- causal mask (only near diagonal)
            int row0 = q0 + wm + g, row1 = row0 + 8;
            if (kv0 + 63 > row0) {
#pragma unroll
                for (int nt = 0; nt < 8; nt++) {
                    int c = kv0 + nt * 8 + 2 * tig;
                    if (c > row0)     acc[nt][0] = NEGINF;
                    if (c + 1 > row0) acc[nt][1] = NEGINF;
                    if (c > row1)     acc[nt][2] = NEGINF;
                    if (c + 1 > row1) acc[nt][3] = NEGINF;
                }
            }

            // ---- online softmax (rows g, g+8)
            float tm0 = NEGINF, tm1 = NEGINF;
#pragma unroll
            for (int nt = 0; nt < 8; nt++) {
                tm0 = fmaxf(tm0, fmaxf(acc[nt][0], acc[nt][1]));
                tm1 = fmaxf(tm1, fmaxf(acc[nt][2], acc[nt][3]));
            }
            tm0 = fmaxf(tm0, __shfl_xor_sync(0xffffffffu, tm0, 1));
            tm0 = fmaxf(tm0, __shfl_xor_sync(0xffffffffu, tm0, 2));
            tm1 = fmaxf(tm1, __shfl_xor_sync(0xffffffffu, tm1, 1));
            tm1 = fmaxf(tm1, __shfl_xor_sync(0xffffffffu, tm1, 2));
            float mn0 = fmaxf(mx0, tm0), mn1 = fmaxf(mx1, tm1);
            float cr0 = __expf(mx0 - mn0), cr1 = __expf(mx1 - mn1);
            mx0 = mn0; mx1 = mn1;
            float rs0 = 0.f, rs1 = 0.f;
#pragma unroll
            for (int nt = 0; nt < 8; nt++) {
                acc[nt][0] = tf32r(__expf(acc[nt][0] - mn0));
                acc[nt][1] = tf32r(__expf(acc[nt][1] - mn0));
                acc[nt][2] = tf32r(__expf(acc[nt][2] - mn1));
                acc[nt][3] = tf32r(__expf(acc[nt][3] - mn1));
                rs0 += acc[nt][0] + acc[nt][1];
                rs1 += acc[nt][2] + acc[nt][3];
            }
            rs0 += __shfl_xor_sync(0xffffffffu, rs0, 1);
            rs0 += __shfl_xor_sync(0xffffffffu, rs0, 2);
            rs1 += __shfl_xor_sync(0xffffffffu, rs1, 1);
            rs1 += __shfl_xor_sync(0xffffffffu, rs1, 2);
            l0 = l0 * cr0 + rs0;
            l1 = l1 * cr1 + rs1;
#pragma unroll
            for (int nt = 0; nt < 8; nt++) {
                o[nt][0] *= cr0; o[nt][1] *= cr0;
                o[nt][2] *= cr1; o[nt][3] *= cr1;
            }

            // ---- P -> smem (warp-private rows), then P @ V
            {
                float* pr0 = pmem + (wm + g) * ASTR + 2 * tig;
                float* pr1 = pr0 + 8 * ASTR;
#pragma unroll
                for (int nt = 0; nt < 8; nt++) {
                    *(float2*)(pr0 + nt * 8) = make_float2(acc[nt][0], acc[nt][1]);
                    *(float2*)(pr1 + nt * 8) = make_float2(acc[nt][2], acc[nt][3]);
                }
            }
            __syncwarp();
            uint32_t vbase = sV + (uint32_t)(buf * KVF) * 4;
#pragma unroll
            for (int kk = 0; kk < 8; kk++) {
                uint32_t pf[4], bv[4][4];
                ldsm4(pf, sP + (uint32_t)(aRowP * ASTR + kk * 8 + aColP) * 4);
#pragma unroll
                for (int np = 0; np < 4; np++)
                    ldsm4(bv[np], vbase + (uint32_t)((np * 16 + bRow) * ASTR + kk * 8 + bCol4) * 4);
#pragma unroll
                for (int nt = 0; nt < 8; nt++)
                    mma_tf32(o[nt], pf, &bv[nt >> 1][(nt & 1) * 2]);
            }
        }
        __syncthreads();
    }

    // ---- epilogue: out[b, t=row, h, dh] = o / l, tf32-rounded for proj GEMM
    float inv0 = 1.f / l0, inv1 = 1.f / l1;
    int r0 = q0 + wm + g;
    float* o0 = out + (size_t)(b * TT + r0) * DD + h * DHH + 2 * tig;
    float* o1 = o0 + (size_t)8 * DD;
#pragma unroll
    for (int nt = 0; nt < 8; nt++) {
        *(float2*)(o0 + nt * 8) = make_float2(tf32r(o[nt][0] * inv0), tf32r(o[nt][1] * inv0));
        *(float2*)(o1 + nt * 8) = make_float2(tf32r(o[nt][2] * inv1), tf32r(o[nt][3] * inv1));
    }
}

// ---------------- silu(gate) * up from combined [M,8192] -> t1 [M,4096] tf32 ---
__global__ void silu_mul_kernel(const float* __restrict__ gu, float* __restrict__ t1) {
    int idx = blockIdx.x * 256 + threadIdx.x;
    int m  = idx >> 10;
    int j4 = idx & 1023;
    const float4* rowp = (const float4*)(gu + (size_t)m * D8);
    float4 a = rowp[j4];
    float4 bV = rowp[j4 + 1024];
    a.x = a.x / (1.f + __expf(-a.x)) * bV.x;
    a.y = a.y / (1.f + __expf(-a.y)) * bV.y;
    a.z = a.z / (1.f + __expf(-a.z)) * bV.z;
    a.w = a.w / (1.f + __expf(-a.w)) * bV.w;
    ((float4*)t1)[idx] = tf32r4(a);
}

// ---------------- launch ------------------------------------------------------
extern "C" void kernel_launch(void* const* d_in, const int* in_sizes, int n_in,
                              void* d_out, int out_size) {
    const float* x       = (const float*)d_in[0];
    const float* w_norm1 = (const float*)d_in[1];
    const float* w_qkv   = (const float*)d_in[2];
    const float* w_proj  = (const float*)d_in[3];
    const float* w_norm2 = (const float*)d_in[4];
    const float* w_gate  = (const float*)d_in[5];
    const float* w_up    = (const float*)d_in[6];
    const float* w_down  = (const float*)d_in[7];

    float* xo = (float*)d_out;
    float* kc = xo + (size_t)MT * DD;
    float* vc = kc + (size_t)BB * HH * TT * DHH;

    float *h, *qkv, *att, *gu, *t1, *wc, *ktp, *vtp;
    cudaGetSymbolAddress((void**)&h,   g_h);
    cudaGetSymbolAddress((void**)&qkv, g_qkv);
    cudaGetSymbolAddress((void**)&att, g_att);
    cudaGetSymbolAddress((void**)&gu,  g_gu);
    cudaGetSymbolAddress((void**)&t1,  g_t1);
    cudaGetSymbolAddress((void**)&wc,  g_wc);
    cudaGetSymbolAddress((void**)&ktp, g_kt);
    cudaGetSymbolAddress((void**)&vtp, g_vt);

    float* wc_qkv  = wc;
    float* wc_proj = wc + (size_t)3 * 1024 * 1024;
    float* wc_gu   = wc + (size_t)4 * 1024 * 1024;
    float* wc_up   = wc_gu + (size_t)4 * 1024 * 1024;
    float* wc_down = wc + (size_t)12 * 1024 * 1024;

    cudaFuncSetAttribute(gemm_tc<0>, cudaFuncAttributeMaxDynamicSharedMemorySize, GEMM_SMEM);
    cudaFuncSetAttribute(gemm_tc<1>, cudaFuncAttributeMaxDynamicSharedMemorySize, GEMM_SMEM);
    cudaFuncSetAttribute(attn_mma,   cudaFuncAttributeMaxDynamicSharedMemorySize, ATT_SMEM);

    // 0. convert weights to tf32 (gate/up stacked)
    cvt_kernel<<<(3 * 1024 * 1024 / 4) / 256, 256>>>(w_qkv,  wc_qkv,  3 * 1024 * 1024 / 4);
    cvt_kernel<<<(1024 * 1024 / 4) / 256,     256>>>(w_proj, wc_proj, 1024 * 1024 / 4);
    cvt_kernel<<<(4 * 1024 * 1024 / 4) / 256, 256>>>(w_gate, wc_gu,   4 * 1024 * 1024 / 4);
    cvt_kernel<<<(4 * 1024 * 1024 / 4) / 256, 256>>>(w_up,   wc_up,   4 * 1024 * 1024 / 4);
    cvt_kernel<<<(4 * 1024 * 1024 / 4) / 256, 256>>>(w_down, wc_down, 4 * 1024 * 1024 / 4);

    // 1. h = tf32(rmsnorm(x) * w1)
    rmsnorm_kernel<<<MT, 256>>>(x, w_norm1, h);
    // 2. qkv = h @ w_qkv^T
    gemm_tc<0><<<dim3(D3 / 128, MT / 128), 256, GEMM_SMEM>>>(h, wc_qkv, qkv, nullptr, MT, D3, DD);
    // 3. scatter k/v: exact caches + tf32 K copy + tf32 V^T copy
    split_kv_kernel<<<(BB * HH * TT * DHH / 4) / 256, 256>>>(qkv, kc, vc, ktp, vtp);
    // 4. tensor-core causal flash attention -> att [b,t,h,dh] (tf32)
    attn_mma<<<dim3(TT / 128, BB * HH), 256, ATT_SMEM>>>(qkv, ktp, vtp, att);
    // 5. x = x + att @ w_proj^T
    gemm_tc<1><<<dim3(DD / 128, MT / 128), 256, GEMM_SMEM>>>(att, wc_proj, xo, x, MT, DD, DD);
    // 6. h = tf32(rmsnorm(x) * w2)
    rmsnorm_kernel<<<MT, 256>>>(xo, w_norm2, h);
    // 7. gate|up combined
    gemm_tc<0><<<dim3(D8 / 128, MT / 128), 256, GEMM_SMEM>>>(h, wc_gu, gu, nullptr, MT, D8, DD);
    // 8. t1 = tf32(silu(gate) * up)
    silu_mul_kernel<<<((size_t)MT * D4 / 4) / 256, 256>>>(gu, t1);
    // 9. x += t1 @ w_down^T
    gemm_tc<1><<<dim3(DD / 128, MT / 128), 256, GEMM_SMEM>>>(t1, wc_down, xo, xo, MT, DD, D4);
}

// round 5
// speedup vs baseline: 10.0175x; 1.5521x over previous
#include <cuda_runtime.h>
#include <cuda_fp16.h>
#include <math.h>
#include <stdint.h>

#define BB   2
#define TT   2048
#define DD   1024
#define HH   16
#define DHH  64
#define MT   4096            // B*T
#define D3   3072            // 3*D
#define D4   4096            // 4*D
#define D8   8192            // gate+up stacked

// ---------------- scratch (static device arrays; no allocation) ----------------
__device__ __half g_h[MT * DD];                      // rmsnorm output (f16)
__device__ float  g_qkv[(size_t)MT * D3];            // qkv projection (fp32, exact)
__device__ __half g_att[MT * DD];                    // attention out (f16)
__device__ __half g_gu[(size_t)MT * D8];             // gate|up combined (f16)
__device__ __half g_t1[(size_t)MT * D4];             // silu(gate)*up (f16)
__device__ __half g_wh[16 * 1024 * 1024];            // converted weights (f16)
__device__ __half g_kt[(size_t)BB * HH * TT * DHH];  // f16 K   [bh][t][dh]
__device__ __half g_vt[(size_t)BB * HH * TT * DHH];  // f16 V^T [bh][dh][t]

// ---------------- helpers -------------------------------------------------------
__device__ __forceinline__ void mma_h(float* c, const uint32_t* a, const uint32_t* b) {
    asm volatile(
        "mma.sync.aligned.m16n8k16.row.col.f32.f16.f16.f32 "
        "{%0,%1,%2,%3}, {%4,%5,%6,%7}, {%8,%9}, {%0,%1,%2,%3};\n"
        : "+f"(c[0]), "+f"(c[1]), "+f"(c[2]), "+f"(c[3])
        : "r"(a[0]), "r"(a[1]), "r"(a[2]), "r"(a[3]), "r"(b[0]), "r"(b[1]));
}
__device__ __forceinline__ void ldsm4(uint32_t* r, uint32_t addr) {
    asm volatile("ldmatrix.sync.aligned.m8n8.x4.shared.b16 {%0,%1,%2,%3}, [%4];"
                 : "=r"(r[0]), "=r"(r[1]), "=r"(r[2]), "=r"(r[3]) : "r"(addr));
}
__device__ __forceinline__ void cpa16(uint32_t dst, const void* src) {
    asm volatile("cp.async.cg.shared.global [%0], [%1], 16;" :: "r"(dst), "l"(src));
}
__device__ __forceinline__ void cp_commit() { asm volatile("cp.async.commit_group;"); }
template <int N>
__device__ __forceinline__ void cp_wait() { asm volatile("cp.async.wait_group %0;" :: "n"(N)); }

__device__ __forceinline__ uint32_t h2u(__half2 h) { return *reinterpret_cast<uint32_t*>(&h); }

// ---------------- weight convert: fp32 -> f16 -----------------------------------
__global__ void cvt_h(const float* __restrict__ src, __half* __restrict__ dst, int n4) {
    int idx = blockIdx.x * 256 + threadIdx.x;
    if (idx >= n4) return;
    float4 v = ((const float4*)src)[idx];
    __half2 a = __floats2half2_rn(v.x, v.y);
    __half2 b = __floats2half2_rn(v.z, v.w);
    ((uint2*)dst)[idx] = make_uint2(h2u(a), h2u(b));
}

// ---------------- RMSNorm (f16 output) ------------------------------------------
__global__ void rmsnorm_kernel(const float* __restrict__ x,
                               const float* __restrict__ w,
                               __half* __restrict__ out) {
    int row = blockIdx.x;
    int t   = threadIdx.x;
    float4 xv = ((const float4*)(x + (size_t)row * DD))[t];
    float s = xv.x * xv.x + xv.y * xv.y + xv.z * xv.z + xv.w * xv.w;
#pragma unroll
    for (int o = 16; o; o >>= 1) s += __shfl_xor_sync(0xffffffffu, s, o);
    __shared__ float red[8];
    __shared__ float rs;
    if ((t & 31) == 0) red[t >> 5] = s;
    __syncthreads();
    if (t == 0) {
        float tot = 0.f;
#pragma unroll
        for (int i = 0; i < 8; i++) tot += red[i];
        rs = rsqrtf(tot * (1.0f / DD) + 1e-6f);
    }
    __syncthreads();
    float r = rs;
    float4 wv = ((const float4*)w)[t];
    __half2 a = __floats2half2_rn(xv.x * r * wv.x, xv.y * r * wv.y);
    __half2 b = __floats2half2_rn(xv.z * r * wv.z, xv.w * r * wv.w);
    ((uint2*)(out + (size_t)row * DD))[t] = make_uint2(h2u(a), h2u(b));
}

// ---------------- f16 tensor-core NT GEMM ---------------------------------------
// C[M,N] = A[M,K] @ B[N,K]^T (+R). Block 128x128, BK=32, 4-stage cp.async,
// 256 thr = 8 warps (2M x 4N), warp tile 64x32, mma m16n8k16.
#define HST 40                       // halves per smem row (32 + 8 pad)
#define HSTG 4
#define GEMMH_SMEM (HSTG * 128 * HST * 2 * 2)   // 81920 B

template <int ADDRES, int OUTHALF>
__global__ void __launch_bounds__(256, 2)
gemm_h(const __half* __restrict__ A, const __half* __restrict__ B,
       void* __restrict__ Cv, const float* __restrict__ R,
       int M, int N, int K) {
    extern __shared__ __half smg[];
    const int AS = 128 * HST;                 // halves per stage per matrix
    uint32_t sA = (uint32_t)__cvta_generic_to_shared(smg);
    uint32_t sB = sA + HSTG * AS * 2;

    int tid  = threadIdx.x;
    int warp = tid >> 5, lane = tid & 31;
    int g = lane >> 2, tig = lane & 3;
    int wm = (warp >> 2) * 64;
    int wn = (warp & 3) * 32;
    int bm = blockIdx.y * 128, bn = blockIdx.x * 128;

    int lr  = tid >> 1;                // 0..127
    int lkh = (tid & 1) * 16;          // 0 or 16 (halves)
    const __half* Ag = A + (size_t)(bm + lr) * K + lkh;
    const __half* Bg = B + (size_t)(bn + lr) * K + lkh;
    uint32_t dA = sA + (uint32_t)(lr * HST + lkh) * 2;
    uint32_t dB = sB + (uint32_t)(lr * HST + lkh) * 2;

    int aRow = wm + (lane & 15);
    int aColH = (lane >> 4) * 8;                        // halves
    int bRow = (lane & 7) + ((lane >> 4) & 1) * 8;
    int bColH = ((lane >> 3) & 1) * 8;                  // halves

    float acc[4][4][4];
#pragma unroll
    for (int i = 0; i < 4; i++)
#pragma unroll
        for (int j = 0; j < 4; j++)
#pragma unroll
            for (int q = 0; q < 4; q++) acc[i][j][q] = 0.f;

#pragma unroll
    for (int s = 0; s < HSTG - 1; s++) {
        uint32_t so = (uint32_t)(s * AS * 2);
        int ko = s * 32;
        cpa16(dA + so,      Ag + ko);
        cpa16(dA + so + 16, Ag + ko + 8);
        cpa16(dB + so,      Bg + ko);
        cpa16(dB + so + 16, Bg + ko + 8);
        cp_commit();
    }

    int rd = 0, wr = HSTG - 1;
    int iters = K >> 5;
    cp_wait<HSTG - 2>();
    __syncthreads();

    for (int it = 0; it < iters; it++) {
        uint32_t stA = sA + (uint32_t)(rd * AS * 2);
        uint32_t stB = sB + (uint32_t)(rd * AS * 2);
#pragma unroll
        for (int kk = 0; kk < 2; kk++) {           // two k16 steps
            uint32_t af[4][4], bf[2][4];
#pragma unroll
            for (int mt = 0; mt < 4; mt++)
                ldsm4(af[mt], stA + (uint32_t)((aRow + mt * 16) * HST + kk * 16 + aColH) * 2);
#pragma unroll
            for (int np = 0; np < 2; np++)
                ldsm4(bf[np], stB + (uint32_t)((wn + np * 16 + bRow) * HST + kk * 16 + bColH) * 2);
#pragma unroll
            for (int mt = 0; mt < 4; mt++)
#pragma unroll
                for (int nt = 0; nt < 4; nt++)
                    mma_h(acc[mt][nt], af[mt], &bf[nt >> 1][(nt & 1) * 2]);
        }
        int nk = (it + HSTG - 1) * 32;
        if (nk < K) {
            uint32_t so = (uint32_t)(wr * AS * 2);
            cpa16(dA + so,      Ag + nk);
            cpa16(dA + so + 16, Ag + nk + 8);
            cpa16(dB + so,      Bg + nk);
            cpa16(dB + so + 16, Bg + nk + 8);
        }
        cp_commit();
        wr = rd;
        rd = (rd + 1) & (HSTG - 1);
        cp_wait<HSTG - 2>();
        __syncthreads();
    }

#pragma unroll
    for (int mt = 0; mt < 4; mt++) {
#pragma unroll
        for (int nt = 0; nt < 4; nt++) {
            int r0 = bm + wm + mt * 16 + g;
            int c0 = bn + wn + nt * 8 + 2 * tig;
            size_t o0 = (size_t)r0 * N + c0;
            size_t o1 = (size_t)(r0 + 8) * N + c0;
            float2 v0 = make_float2(acc[mt][nt][0], acc[mt][nt][1]);
            float2 v1 = make_float2(acc[mt][nt][2], acc[mt][nt][3]);
            if (ADDRES) {
                float2 r4 = *(const float2*)(R + o0);
                v0.x += r4.x; v0.y += r4.y;
                float2 r5 = *(const float2*)(R + o1);
                v1.x += r5.x; v1.y += r5.y;
            }
            if (OUTHALF) {
                __half* C = (__half*)Cv;
                *(__half2*)(C + o0) = __floats2half2_rn(v0.x, v0.y);
                *(__half2*)(C + o1) = __floats2half2_rn(v1.x, v1.y);
            } else {
                float* C = (float*)Cv;
                *(float2*)(C + o0) = v0;
                *(float2*)(C + o1) = v1;
            }
        }
    }
}

// ---------------- split qkv -> kc/vc (fp32 exact) + kt (f16) + vt (f16 transposed)
// block: 64 tokens of one bh; 256 threads. smem transpose for vt.
__global__ void split_kv_kernel(const float* __restrict__ qkv,
                                float* __restrict__ kc, float* __restrict__ vc,
                                __half* __restrict__ kt, __half* __restrict__ vt) {
    __shared__ __half sv[64][72];
    int tb = blockIdx.x;            // 0..31  (t chunk)
    int bh = blockIdx.y;            // 0..31
    int b = bh >> 4, h = bh & 15;
    int tid = threadIdx.x;
    int r  = tid >> 2;              // token in tile 0..63
    int cb = (tid & 3) * 16;        // dh start
    int t0 = tb * 64;

    const float* src = qkv + (size_t)(b * TT + t0 + r) * D3 + DD + h * DHH + cb;
    float*  kcd = kc + ((size_t)bh * TT + t0 + r) * DHH + cb;
    float*  vcd = vc + ((size_t)bh * TT + t0 + r) * DHH + cb;
    __half* ktd = kt + ((size_t)bh * TT + t0 + r) * DHH + cb;
#pragma unroll
    for (int i = 0; i < 4; i++) {
        float4 k4 = *(const float4*)(src + 4 * i);
        float4 v4 = *(const float4*)(src + DD + 4 * i);
        *(float4*)(kcd + 4 * i) = k4;
        *(float4*)(vcd + 4 * i) = v4;
        *(uint2*)(ktd + 4 * i) = make_uint2(h2u(__floats2half2_rn(k4.x, k4.y)),
                                            h2u(__floats2half2_rn(k4.z, k4.w)));
        sv[r][cb + 4 * i + 0] = __float2half_rn(v4.x);
        sv[r][cb + 4 * i + 1] = __float2half_rn(v4.y);
        sv[r][cb + 4 * i + 2] = __float2half_rn(v4.z);
        sv[r][cb + 4 * i + 3] = __float2half_rn(v4.w);
    }
    __syncthreads();
    // transpose out: thread handles dh row dr, 16 consecutive t
    int dr = tid >> 2;
    int tc = (tid & 3) * 16;
    __half* dst = vt + ((size_t)bh * DHH + dr) * TT + t0 + tc;
#pragma unroll
    for (int i = 0; i < 16; i += 2) {
        __half2 p = __halves2half2(sv[tc + i][dr], sv[tc + i + 1][dr]);
        *(__half2*)(dst + i) = p;
    }
}

// ---------------- f16 tensor-core flash attention --------------------------------
// Q-tile 128, KV-tile 64, 8 warps; warp w owns S rows wm..wm+15 (64 kv cols).
#define HATR 72
#define HKVF (64 * HATR)
#define ATTH_SMEM ((4 * HKVF + 128 * HATR) * 2)
#define NEGINF __int_as_float(0xff800000)

__global__ void __launch_bounds__(256, 2)
attn_mma(const float* __restrict__ qkv, const __half* __restrict__ kt,
         const __half* __restrict__ vt, __half* __restrict__ out) {
    extern __shared__ __half smh[];
    uint32_t sbase = (uint32_t)__cvta_generic_to_shared(smh);
    const uint32_t sK = sbase;
    const uint32_t sV = sbase + 2 * HKVF * 2;
    const uint32_t sP = sbase + 4 * HKVF * 2;
    __half* pmem = smh + 4 * HKVF;

    int qt = (int)(gridDim.x - 1) - (int)blockIdx.x;
    int bh = blockIdx.y;
    int b = bh >> 4, h = bh & 15;
    int q0 = qt * 128;
    int tid = threadIdx.x;
    int warp = tid >> 5, lane = tid & 31;
    int g = lane >> 2, tig = lane & 3;
    int wm = warp * 16;

    const __half* ktb = kt + (size_t)bh * TT * DHH;     // [t][dh]
    const __half* vtb = vt + (size_t)bh * DHH * TT;     // [dh][t]

    // ---- stage Q tile (scaled, f16) into sP, extract warp A-frags --------------
    {
        int row = tid >> 1;
        int c0 = (tid & 1) * 32;
        const float* src = qkv + ((size_t)(b * TT + q0 + row)) * D3 + h * DHH + c0;
        __half* dst = pmem + row * HATR + c0;
#pragma unroll
        for (int j = 0; j < 4; j++) {
            float4 v1 = *(const float4*)(src + 8 * j);
            float4 v2 = *(const float4*)(src + 8 * j + 4);
            uint4 u;
            u.x = h2u(__floats2half2_rn(v1.x * 0.125f, v1.y * 0.125f));
            u.y = h2u(__floats2half2_rn(v1.z * 0.125f, v1.w * 0.125f));
            u.z = h2u(__floats2half2_rn(v2.x * 0.125f, v2.y * 0.125f));
            u.w = h2u(__floats2half2_rn(v2.z * 0.125f, v2.w * 0.125f));
            *(uint4*)(dst + 8 * j) = u;
        }
    }
    __syncthreads();
    uint32_t qf[4][4];
    {
        int aRow = wm + (lane & 15);
        int aColH = (lane >> 4) * 8;
#pragma unroll
        for (int kk = 0; kk < 4; kk++)
            ldsm4(qf[kk], sP + (uint32_t)(aRow * HATR + kk * 16 + aColH) * 2);
    }
    __syncthreads();

    float o[8][4];
#pragma unroll
    for (int nt = 0; nt < 8; nt++)
#pragma unroll
        for (int i = 0; i < 4; i++) o[nt][i] = 0.f;
    float mx0 = -1e30f, mx1 = -1e30f, l0 = 0.f, l1 = 0.f;

    int nT = 2 * qt + 2;
    int bRow = (lane & 7) + ((lane >> 4) & 1) * 8;
    int bColH = ((lane >> 3) & 1) * 8;
    int aRowP = wm + (lane & 15);
    int aColP = (lane >> 4) * 8;

    auto load_tile = [&](int jt, int s) {
        int kv = jt * 64;
        int r = tid >> 2;
        int cbh = (tid & 3) * 16;
        const __half* ksrc = ktb + (size_t)(kv + r) * DHH + cbh;
        const __half* vsrc = vtb + (size_t)r * TT + kv + cbh;
        uint32_t kd = sK + (uint32_t)(s * HKVF + r * HATR + cbh) * 2;
        uint32_t vd = sV + (uint32_t)(s * HKVF + r * HATR + cbh) * 2;
        cpa16(kd,      ksrc);
        cpa16(kd + 16, ksrc + 8);
        cpa16(vd,      vsrc);
        cpa16(vd + 16, vsrc + 8);
    };

    load_tile(0, 0);
    cp_commit();

    for (int jt = 0; jt < nT; jt++) {
        int buf = jt & 1;
        if (jt + 1 < nT) { load_tile(jt + 1, buf ^ 1); cp_commit(); cp_wait<1>(); }
        else             { cp_commit(); cp_wait<0>(); }
        __syncthreads();

        int kv0 = jt * 64;
        if (kv0 <= q0 + wm + 15) {
            // ---- S = Q @ K^T
            float acc[8][4];
#pragma unroll
            for (int nt = 0; nt < 8; nt++)
#pragma unroll
                for (int i = 0; i < 4; i++) acc[nt][i] = 0.f;
            uint32_t kbase = sK + (uint32_t)(buf * HKVF) * 2;
#pragma unroll
            for (int kk = 0; kk < 4; kk++) {
                uint32_t bf[4][4];
#pragma unroll
                for (int np = 0; np < 4; np++)
                    ldsm4(bf[np], kbase + (uint32_t)((np * 16 + bRow) * HATR + kk * 16 + bColH) * 2);
#pragma unroll
                for (int nt = 0; nt < 8; nt++)
                    mma_h(acc[nt], qf[kk], &bf[nt >> 1][(nt & 1) * 2]);
            }

            // ---- causal mask
            int row0 = q0 + wm + g, row1 = row0 + 8;
            if (kv0 + 63 > row0) {
#pragma unroll
                for (int nt = 0; nt < 8; nt++) {
                    int c = kv0 + nt * 8 + 2 * tig;
                    if (c > row0)     acc[nt][0] = NEGINF;
                    if (c + 1 > row0) acc[nt][1] = NEGINF;
                    if (c > row1)     acc[nt][2] = NEGINF;
                    if (c + 1 > row1) acc[nt][3] = NEGINF;
                }
            }

            // ---- online softmax (rows g, g+8); P rounded to f16 consistently
            float tm0 = NEGINF, tm1 = NEGINF;
#pragma unroll
            for (int nt = 0; nt < 8; nt++) {
                tm0 = fmaxf(tm0, fmaxf(acc[nt][0], acc[nt][1]));
                tm1 = fmaxf(tm1, fmaxf(acc[nt][2], acc[nt][3]));
            }
            tm0 = fmaxf(tm0, __shfl_xor_sync(0xffffffffu, tm0, 1));
            tm0 = fmaxf(tm0, __shfl_xor_sync(0xffffffffu, tm0, 2));
            tm1 = fmaxf(tm1, __shfl_xor_sync(0xffffffffu, tm1, 1));
            tm1 = fmaxf(tm1, __shfl_xor_sync(0xffffffffu, tm1, 2));
            float mn0 = fmaxf(mx0, tm0), mn1 = fmaxf(mx1, tm1);
            float cr0 = __expf(mx0 - mn0), cr1 = __expf(mx1 - mn1);
            mx0 = mn0; mx1 = mn1;
            float rs0 = 0.f, rs1 = 0.f;
            __half2* pr0 = (__half2*)(pmem + (wm + g) * HATR + 2 * tig);
            __half2* pr1 = (__half2*)(pmem + (wm + g + 8) * HATR + 2 * tig);
#pragma unroll
            for (int nt = 0; nt < 8; nt++) {
                __half2 p0 = __floats2half2_rn(__expf(acc[nt][0] - mn0), __expf(acc[nt][1] - mn0));
                __half2 p1 = __floats2half2_rn(__expf(acc[nt][2] - mn1), __expf(acc[nt][3] - mn1));
                pr0[nt * 4] = p0;      // nt*8 halves = nt*4 half2
                pr1[nt * 4] = p1;
                float2 f0 = __half22float2(p0);
                float2 f1 = __half22float2(p1);
                rs0 += f0.x + f0.y;
                rs1 += f1.x + f1.y;
            }
            rs0 += __shfl_xor_sync(0xffffffffu, rs0, 1);
            rs0 += __shfl_xor_sync(0xffffffffu, rs0, 2);
            rs1 += __shfl_xor_sync(0xffffffffu, rs1, 1);
            rs1 += __shfl_xor_sync(0xffffffffu, rs1, 2);
            l0 = l0 * cr0 + rs0;
            l1 = l1 * cr1 + rs1;
#pragma unroll
            for (int nt = 0; nt < 8; nt++) {
                o[nt][0] *= cr0; o[nt][1] *= cr0;
                o[nt][2] *= cr1; o[nt][3] *= cr1;
            }
            __syncwarp();

            // ---- P @ V
            uint32_t vbase = sV + (uint32_t)(buf * HKVF) * 2;
#pragma unroll
            for (int kk = 0; kk < 4; kk++) {
                uint32_t pf[4], bv[4][4];
                ldsm4(pf, sP + (uint32_t)(aRowP * HATR + kk * 16 + aColP) * 2);
#pragma unroll
                for (int np = 0; np < 4; np++)
                    ldsm4(bv[np], vbase + (uint32_t)((np * 16 + bRow) * HATR + kk * 16 + bColH) * 2);
#pragma unroll
                for (int nt = 0; nt < 8; nt++)
                    mma_h(o[nt], pf, &bv[nt >> 1][(nt & 1) * 2]);
            }
        }
        __syncthreads();
    }

    // ---- epilogue: out[b, t, h, dh] = o / l as f16
    float inv0 = 1.f / l0, inv1 = 1.f / l1;
    int r0 = q0 + wm + g;
    __half* o0 = out + (size_t)(b * TT + r0) * DD + h * DHH + 2 * tig;
    __half* o1 = o0 + (size_t)8 * DD;
#pragma unroll
    for (int nt = 0; nt < 8; nt++) {
        *(__half2*)(o0 + nt * 8) = __floats2half2_rn(o[nt][0] * inv0, o[nt][1] * inv0);
        *(__half2*)(o1 + nt * 8) = __floats2half2_rn(o[nt][2] * inv1, o[nt][3] * inv1);
    }
}

// ---------------- silu(gate) * up: gu f16 [M,8192] -> t1 f16 [M,4096] -----------
__global__ void silu_mul_kernel(const __half* __restrict__ gu, __half* __restrict__ t1) {
    int idx = blockIdx.x * 256 + threadIdx.x;       // half2 index into t1
    int m  = idx >> 11;                             // 2048 half2 per row
    int j2 = idx & 2047;
    const __half2* rowp = (const __half2*)(gu + (size_t)m * D8);
    float2 a = __half22float2(rowp[j2]);
    float2 u = __half22float2(rowp[j2 + 2048]);
    a.x = a.x / (1.f + __expf(-a.x)) * u.x;
    a.y = a.y / (1.f + __expf(-a.y)) * u.y;
    ((__half2*)t1)[idx] = __floats2half2_rn(a.x, a.y);
}

// ---------------- launch --------------------------------------------------------
extern "C" void kernel_launch(void* const* d_in, const int* in_sizes, int n_in,
                              void* d_out, int out_size) {
    const float* x       = (const float*)d_in[0];
    const float* w_norm1 = (const float*)d_in[1];
    const float* w_qkv   = (const float*)d_in[2];
    const float* w_proj  = (const float*)d_in[3];
    const float* w_norm2 = (const float*)d_in[4];
    const float* w_gate  = (const float*)d_in[5];
    const float* w_up    = (const float*)d_in[6];
    const float* w_down  = (const float*)d_in[7];

    float* xo = (float*)d_out;
    float* kc = xo + (size_t)MT * DD;
    float* vc = kc + (size_t)BB * HH * TT * DHH;

    __half *h, *att, *gu, *t1, *wh, *ktp, *vtp;
    float *qkv;
    cudaGetSymbolAddress((void**)&h,   g_h);
    cudaGetSymbolAddress((void**)&qkv, g_qkv);
    cudaGetSymbolAddress((void**)&att, g_att);
    cudaGetSymbolAddress((void**)&gu,  g_gu);
    cudaGetSymbolAddress((void**)&t1,  g_t1);
    cudaGetSymbolAddress((void**)&wh,  g_wh);
    cudaGetSymbolAddress((void**)&ktp, g_kt);
    cudaGetSymbolAddress((void**)&vtp, g_vt);

    __half* wh_qkv  = wh;
    __half* wh_proj = wh + (size_t)3 * 1024 * 1024;
    __half* wh_gu   = wh + (size_t)4 * 1024 * 1024;
    __half* wh_up   = wh_gu + (size_t)4 * 1024 * 1024;
    __half* wh_down = wh + (size_t)12 * 1024 * 1024;

    cudaFuncSetAttribute(gemm_h<0,0>, cudaFuncAttributeMaxDynamicSharedMemorySize, GEMMH_SMEM);
    cudaFuncSetAttribute(gemm_h<1,0>, cudaFuncAttributeMaxDynamicSharedMemorySize, GEMMH_SMEM);
    cudaFuncSetAttribute(gemm_h<0,1>, cudaFuncAttributeMaxDynamicSharedMemorySize, GEMMH_SMEM);
    cudaFuncSetAttribute(attn_mma,    cudaFuncAttributeMaxDynamicSharedMemorySize, ATTH_SMEM);

    // 0. convert weights to f16 (gate/up stacked)
    cvt_h<<<(3 * 1024 * 1024 / 4) / 256, 256>>>(w_qkv,  wh_qkv,  3 * 1024 * 1024 / 4);
    cvt_h<<<(1024 * 1024 / 4) / 256,     256>>>(w_proj, wh_proj, 1024 * 1024 / 4);
    cvt_h<<<(4 * 1024 * 1024 / 4) / 256, 256>>>(w_gate, wh_gu,   4 * 1024 * 1024 / 4);
    cvt_h<<<(4 * 1024 * 1024 / 4) / 256, 256>>>(w_up,   wh_up,   4 * 1024 * 1024 / 4);
    cvt_h<<<(4 * 1024 * 1024 / 4) / 256, 256>>>(w_down, wh_down, 4 * 1024 * 1024 / 4);

    // 1. h = f16(rmsnorm(x) * w1)
    rmsnorm_kernel<<<MT, 256>>>(x, w_norm1, h);
    // 2. qkv = h @ w_qkv^T  (fp32 out)
    gemm_h<0,0><<<dim3(D3 / 128, MT / 128), 256, GEMMH_SMEM>>>(h, wh_qkv, qkv, nullptr, MT, D3, DD);
    // 3. caches (fp32 exact) + f16 K + f16 V^T
    split_kv_kernel<<<dim3(TT / 64, BB * HH), 256>>>(qkv, kc, vc, ktp, vtp);
    // 4. f16 tensor-core causal flash attention -> att (f16)
    attn_mma<<<dim3(TT / 128, BB * HH), 256, ATTH_SMEM>>>(qkv, ktp, vtp, att);
    // 5. x = x + att @ w_proj^T
    gemm_h<1,0><<<dim3(DD / 128, MT / 128), 256, GEMMH_SMEM>>>(att, wh_proj, xo, x, MT, DD, DD);
    // 6. h = f16(rmsnorm(x) * w2)
    rmsnorm_kernel<<<MT, 256>>>(xo, w_norm2, h);
    // 7. gate|up combined (f16 out)
    gemm_h<0,1><<<dim3(D8 / 128, MT / 128), 256, GEMMH_SMEM>>>(h, wh_gu, gu, nullptr, MT, D8, DD);
    // 8. t1 = f16(silu(gate) * up)
    silu_mul_kernel<<<((size_t)MT * D4 / 2) / 256, 256>>>(gu, t1);
    // 9. x += t1 @ w_down^T
    gemm_h<1,0><<<dim3(DD / 128, MT / 128), 256, GEMMH_SMEM>>>(t1, wh_down, xo, xo, MT, DD, D4);
}

// round 7
// speedup vs baseline: 10.6715x; 1.0653x over previous
#include <cuda_runtime.h>
#include <cuda_fp16.h>
#include <math.h>
#include <stdint.h>

#define BB   2
#define TT   2048
#define DD   1024
#define HH   16
#define DHH  64
#define MT   4096            // B*T
#define D3   3072            // 3*D
#define D4   4096            // 4*D
#define D8   8192            // gate+up stacked

// ---------------- scratch (static device arrays; no allocation) ----------------
__device__ __half g_h[MT * DD];                      // rmsnorm output (f16)
__device__ float  g_qkv[(size_t)MT * D3];            // qkv projection (fp32, exact)
__device__ __half g_att[MT * DD];                    // attention out (f16)
__device__ __half g_gu[(size_t)MT * D8];             // gate|up combined (f16)
__device__ __half g_t1[(size_t)MT * D4];             // silu(gate)*up (f16)
__device__ __half g_wh[16 * 1024 * 1024];            // converted weights (f16)
__device__ __half g_kt[(size_t)BB * HH * TT * DHH];  // f16 K   [bh][t][dh]
__device__ __half g_vt[(size_t)BB * HH * TT * DHH];  // f16 V^T [bh][dh][t]

// ---------------- helpers -------------------------------------------------------
__device__ __forceinline__ void mma_h(float* c, const uint32_t* a, const uint32_t* b) {
    asm volatile(
        "mma.sync.aligned.m16n8k16.row.col.f32.f16.f16.f32 "
        "{%0,%1,%2,%3}, {%4,%5,%6,%7}, {%8,%9}, {%0,%1,%2,%3};\n"
        : "+f"(c[0]), "+f"(c[1]), "+f"(c[2]), "+f"(c[3])
        : "r"(a[0]), "r"(a[1]), "r"(a[2]), "r"(a[3]), "r"(b[0]), "r"(b[1]));
}
__device__ __forceinline__ void ldsm4(uint32_t* r, uint32_t addr) {
    asm volatile("ldmatrix.sync.aligned.m8n8.x4.shared.b16 {%0,%1,%2,%3}, [%4];"
                 : "=r"(r[0]), "=r"(r[1]), "=r"(r[2]), "=r"(r[3]) : "r"(addr));
}
__device__ __forceinline__ void cpa16(uint32_t dst, const void* src) {
    asm volatile("cp.async.cg.shared.global [%0], [%1], 16;" :: "r"(dst), "l"(src));
}
__device__ __forceinline__ void cp_commit() { asm volatile("cp.async.commit_group;"); }
template <int N>
__device__ __forceinline__ void cp_wait() { asm volatile("cp.async.wait_group %0;" :: "n"(N)); }
__device__ __forceinline__ uint32_t h2u(__half2 h) { return *reinterpret_cast<uint32_t*>(&h); }

// ---------------- fused weight convert: all 5 weights -> g_wh (f16) -------------
// dst layout (halves): [0,3M) qkv | [3M,4M) proj | [4M,8M) gate | [8M,12M) up | [12M,16M) down
__global__ void cvt_all(const float* __restrict__ wqkv, const float* __restrict__ wproj,
                        const float* __restrict__ wgate, const float* __restrict__ wup,
                        const float* __restrict__ wdown, __half* __restrict__ dst) {
    int idx = blockIdx.x * 256 + threadIdx.x;            // uint2 (=float4) index, 0..4M-1
    const float* src;
    int base;
    if      (idx < (3 << 18))  { src = wqkv;  base = 0; }            // 768K float4
    else if (idx < (4 << 18))  { src = wproj; base = 3 << 18; }
    else if (idx < (8 << 18))  { src = wgate; base = 4 << 18; }
    else if (idx < (12 << 18)) { src = wup;   base = 8 << 18; }
    else                       { src = wdown; base = 12 << 18; }
    float4 v = ((const float4*)src)[idx - base];
    __half2 a = __floats2half2_rn(v.x, v.y);
    __half2 b = __floats2half2_rn(v.z, v.w);
    ((uint2*)dst)[idx] = make_uint2(h2u(a), h2u(b));
}

// ---------------- RMSNorm (f16 output) ------------------------------------------
__global__ void rmsnorm_kernel(const float* __restrict__ x,
                               const float* __restrict__ w,
                               __half* __restrict__ out) {
    int row = blockIdx.x;
    int t   = threadIdx.x;
    float4 xv = ((const float4*)(x + (size_t)row * DD))[t];
    float s = xv.x * xv.x + xv.y * xv.y + xv.z * xv.z + xv.w * xv.w;
#pragma unroll
    for (int o = 16; o; o >>= 1) s += __shfl_xor_sync(0xffffffffu, s, o);
    __shared__ float red[8];
    __shared__ float rs;
    if ((t & 31) == 0) red[t >> 5] = s;
    __syncthreads();
    if (t == 0) {
        float tot = 0.f;
#pragma unroll
        for (int i = 0; i < 8; i++) tot += red[i];
        rs = rsqrtf(tot * (1.0f / DD) + 1e-6f);
    }
    __syncthreads();
    float r = rs;
    float4 wv = ((const float4*)w)[t];
    __half2 a = __floats2half2_rn(xv.x * r * wv.x, xv.y * r * wv.y);
    __half2 b = __floats2half2_rn(xv.z * r * wv.z, xv.w * r * wv.w);
    ((uint2*)(out + (size_t)row * DD))[t] = make_uint2(h2u(a), h2u(b));
}

// ---------------- f16 tensor-core NT GEMM, 128(M) x 256(N) tiles ----------------
// C[M,N] = A[M,K] @ B[N,K]^T (+R). 512 thr = 16 warps (4M x 4N), warp tile 32x64,
// BK=32, 4-stage cp.async pipeline, mma m16n8k16.
#define HST 40                       // halves per smem row (32 + 8 pad)
#define HSTG 4
#define G_AROWS 128
#define G_BROWS 256
#define G_AH (G_AROWS * HST)         // halves per A stage
#define G_BH (G_BROWS * HST)         // halves per B stage
#define GEMMH_SMEM (HSTG * (G_AH + G_BH) * 2)   // 122880 B

template <int ADDRES, int OUTHALF>
__global__ void __launch_bounds__(512, 1)
gemm_h(const __half* __restrict__ A, const __half* __restrict__ B,
       void* __restrict__ Cv, const float* __restrict__ R,
       int M, int N, int K) {
    extern __shared__ __half smg[];
    uint32_t sA = (uint32_t)__cvta_generic_to_shared(smg);
    uint32_t sB = sA + HSTG * G_AH * 2;

    int tid  = threadIdx.x;
    int warp = tid >> 5, lane = tid & 31;
    int g = lane >> 2, tig = lane & 3;
    int wm = (warp >> 2) * 32;          // 0,32,64,96
    int wn = (warp & 3) * 64;           // 0,64,128,192
    int bm = blockIdx.y * 128, bn = blockIdx.x * 256;

    // A loader: 4 thr/row, 8 halves each (1 cpa)
    int alr = tid >> 2;                 // 0..127
    int alk = (tid & 3) * 8;            // 0,8,16,24 halves
    const __half* Ag = A + (size_t)(bm + alr) * K + alk;
    uint32_t dA = sA + (uint32_t)(alr * HST + alk) * 2;
    // B loader: 2 thr/row, 16 halves each (2 cpa)
    int blr = tid >> 1;                 // 0..255
    int blk = (tid & 1) * 16;           // 0,16
    const __half* Bg = B + (size_t)(bn + blr) * K + blk;
    uint32_t dB = sB + (uint32_t)(blr * HST + blk) * 2;

    int aRow = wm + (lane & 15);
    int aColH = (lane >> 4) * 8;
    int bRow = (lane & 7) + ((lane >> 4) & 1) * 8;
    int bColH = ((lane >> 3) & 1) * 8;

    float acc[2][8][4];
#pragma unroll
    for (int i = 0; i < 2; i++)
#pragma unroll
        for (int j = 0; j < 8; j++)
#pragma unroll
            for (int q = 0; q < 4; q++) acc[i][j][q] = 0.f;

#pragma unroll
    for (int s = 0; s < HSTG - 1; s++) {
        uint32_t ao = (uint32_t)(s * G_AH * 2);
        uint32_t bo = (uint32_t)(s * G_BH * 2);
        int ko = s * 32;
        cpa16(dA + ao,      Ag + ko);
        cpa16(dB + bo,      Bg + ko);
        cpa16(dB + bo + 16, Bg + ko + 8);
        cp_commit();
    }

    int rd = 0, wr = HSTG - 1;
    int iters = K >> 5;
    cp_wait<HSTG - 2>();
    __syncthreads();

    for (int it = 0; it < iters; it++) {
        uint32_t stA = sA + (uint32_t)(rd * G_AH * 2);
        uint32_t stB = sB + (uint32_t)(rd * G_BH * 2);
#pragma unroll
        for (int kk = 0; kk < 2; kk++) {           // two k16 steps
            uint32_t af[2][4], bf[4][4];
#pragma unroll
            for (int mt = 0; mt < 2; mt++)
                ldsm4(af[mt], stA + (uint32_t)((aRow + mt * 16) * HST + kk * 16 + aColH) * 2);
#pragma unroll
            for (int np = 0; np < 4; np++)
                ldsm4(bf[np], stB + (uint32_t)((wn + np * 16 + bRow) * HST + kk * 16 + bColH) * 2);
#pragma unroll
            for (int mt = 0; mt < 2; mt++)
#pragma unroll
                for (int nt = 0; nt < 8; nt++)
                    mma_h(acc[mt][nt], af[mt], &bf[nt >> 1][(nt & 1) * 2]);
        }
        int nk = (it + HSTG - 1) * 32;
        if (nk < K) {
            uint32_t ao = (uint32_t)(wr * G_AH * 2);
            uint32_t bo = (uint32_t)(wr * G_BH * 2);
            cpa16(dA + ao,      Ag + nk);
            cpa16(dB + bo,      Bg + nk);
            cpa16(dB + bo + 16, Bg + nk + 8);
        }
        cp_commit();
        wr = rd;
        rd = (rd + 1) & (HSTG - 1);
        cp_wait<HSTG - 2>();
        __syncthreads();
    }

#pragma unroll
    for (int mt = 0; mt < 2; mt++) {
#pragma unroll
        for (int nt = 0; nt < 8; nt++) {
            int r0 = bm + wm + mt * 16 + g;
            int c0 = bn + wn + nt * 8 + 2 * tig;
            size_t o0 = (size_t)r0 * N + c0;
            size_t o1 = (size_t)(r0 + 8) * N + c0;
            float2 v0 = make_float2(acc[mt][nt][0], acc[mt][nt][1]);
            float2 v1 = make_float2(acc[mt][nt][2], acc[mt][nt][3]);
            if (ADDRES) {
                float2 r4 = *(const float2*)(R + o0);
                v0.x += r4.x; v0.y += r4.y;
                float2 r5 = *(const float2*)(R + o1);
                v1.x += r5.x; v1.y += r5.y;
            }
            if (OUTHALF) {
                __half* C = (__half*)Cv;
                *(__half2*)(C + o0) = __floats2half2_rn(v0.x, v0.y);
                *(__half2*)(C + o1) = __floats2half2_rn(v1.x, v1.y);
            } else {
                float* C = (float*)Cv;
                *(float2*)(C + o0) = v0;
                *(float2*)(C + o1) = v1;
            }
        }
    }
}

// ---------------- split qkv -> kc/vc (fp32 exact) + kt (f16) + vt (f16 transposed)
__global__ void split_kv_kernel(const float* __restrict__ qkv,
                                float* __restrict__ kc, float* __restrict__ vc,
                                __half* __restrict__ kt, __half* __restrict__ vt) {
    __shared__ __half sv[64][72];
    int tb = blockIdx.x;
    int bh = blockIdx.y;
    int b = bh >> 4, h = bh & 15;
    int tid = threadIdx.x;
    int r  = tid >> 2;
    int cb = (tid & 3) * 16;
    int t0 = tb * 64;

    const float* src = qkv + (size_t)(b * TT + t0 + r) * D3 + DD + h * DHH + cb;
    float*  kcd = kc + ((size_t)bh * TT + t0 + r) * DHH + cb;
    float*  vcd = vc + ((size_t)bh * TT + t0 + r) * DHH + cb;
    __half* ktd = kt + ((size_t)bh * TT + t0 + r) * DHH + cb;
#pragma unroll
    for (int i = 0; i < 4; i++) {
        float4 k4 = *(const float4*)(src + 4 * i);
        float4 v4 = *(const float4*)(src + DD + 4 * i);
        *(float4*)(kcd + 4 * i) = k4;
        *(float4*)(vcd + 4 * i) = v4;
        *(uint2*)(ktd + 4 * i) = make_uint2(h2u(__floats2half2_rn(k4.x, k4.y)),
                                            h2u(__floats2half2_rn(k4.z, k4.w)));
        sv[r][cb + 4 * i + 0] = __float2half_rn(v4.x);
        sv[r][cb + 4 * i + 1] = __float2half_rn(v4.y);
        sv[r][cb + 4 * i + 2] = __float2half_rn(v4.z);
        sv[r][cb + 4 * i + 3] = __float2half_rn(v4.w);
    }
    __syncthreads();
    int dr = tid >> 2;
    int tc = (tid & 3) * 16;
    __half* dst = vt + ((size_t)bh * DHH + dr) * TT + t0 + tc;
#pragma unroll
    for (int i = 0; i < 16; i += 2) {
        __half2 p = __halves2half2(sv[tc + i][dr], sv[tc + i + 1][dr]);
        *(__half2*)(dst + i) = p;
    }
}

// ---------------- f16 tensor-core flash attention --------------------------------
#define HATR 72
#define HKVF (64 * HATR)
#define ATTH_SMEM ((4 * HKVF + 128 * HATR) * 2)
#define NEGINF __int_as_float(0xff800000)

__global__ void __launch_bounds__(256, 2)
attn_mma(const float* __restrict__ qkv, const __half* __restrict__ kt,
         const __half* __restrict__ vt, __half* __restrict__ out) {
    extern __shared__ __half smh[];
    uint32_t sbase = (uint32_t)__cvta_generic_to_shared(smh);
    const uint32_t sK = sbase;
    const uint32_t sV = sbase + 2 * HKVF * 2;
    const uint32_t sP = sbase + 4 * HKVF * 2;
    __half* pmem = smh + 4 * HKVF;

    int qt = (int)(gridDim.x - 1) - (int)blockIdx.x;
    int bh = blockIdx.y;
    int b = bh >> 4, h = bh & 15;
    int q0 = qt * 128;
    int tid = threadIdx.x;
    int warp = tid >> 5, lane = tid & 31;
    int g = lane >> 2, tig = lane & 3;
    int wm = warp * 16;

    const __half* ktb = kt + (size_t)bh * TT * DHH;
    const __half* vtb = vt + (size_t)bh * DHH * TT;

    {
        int row = tid >> 1;
        int c0 = (tid & 1) * 32;
        const float* src = qkv + ((size_t)(b * TT + q0 + row)) * D3 + h * DHH + c0;
        __half* dst = pmem + row * HATR + c0;
#pragma unroll
        for (int j = 0; j < 4; j++) {
            float4 v1 = *(const float4*)(src + 8 * j);
            float4 v2 = *(const float4*)(src + 8 * j + 4);
            uint4 u;
            u.x = h2u(__floats2half2_rn(v1.x * 0.125f, v1.y * 0.125f));
            u.y = h2u(__floats2half2_rn(v1.z * 0.125f, v1.w * 0.125f));
            u.z = h2u(__floats2half2_rn(v2.x * 0.125f, v2.y * 0.125f));
            u.w = h2u(__floats2half2_rn(v2.z * 0.125f, v2.w * 0.125f));
            *(uint4*)(dst + 8 * j) = u;
        }
    }
    __syncthreads();
    uint32_t qf[4][4];
    {
        int aRow = wm + (lane & 15);
        int aColH = (lane >> 4) * 8;
#pragma unroll
        for (int kk = 0; kk < 4; kk++)
            ldsm4(qf[kk], sP + (uint32_t)(aRow * HATR + kk * 16 + aColH) * 2);
    }
    __syncthreads();

    float o[8][4];
#pragma unroll
    for (int nt = 0; nt < 8; nt++)
#pragma unroll
        for (int i = 0; i < 4; i++) o[nt][i] = 0.f;
    float mx0 = -1e30f, mx1 = -1e30f, l0 = 0.f, l1 = 0.f;

    int nT = 2 * qt + 2;
    int bRow = (lane & 7) + ((lane >> 4) & 1) * 8;
    int bColH = ((lane >> 3) & 1) * 8;
    int aRowP = wm + (lane & 15);
    int aColP = (lane >> 4) * 8;

    auto load_tile = [&](int jt, int s) {
        int kv = jt * 64;
        int r = tid >> 2;
        int cbh = (tid & 3) * 16;
        const __half* ksrc = ktb + (size_t)(kv + r) * DHH + cbh;
        const __half* vsrc = vtb + (size_t)r * TT + kv + cbh;
        uint32_t kd = sK + (uint32_t)(s * HKVF + r * HATR + cbh) * 2;
        uint32_t vd = sV + (uint32_t)(s * HKVF + r * HATR + cbh) * 2;
        cpa16(kd,      ksrc);
        cpa16(kd + 16, ksrc + 8);
        cpa16(vd,      vsrc);
        cpa16(vd + 16, vsrc + 8);
    };

    load_tile(0, 0);
    cp_commit();

    for (int jt = 0; jt < nT; jt++) {
        int buf = jt & 1;
        if (jt + 1 < nT) { load_tile(jt + 1, buf ^ 1); cp_commit(); cp_wait<1>(); }
        else             { cp_commit(); cp_wait<0>(); }
        __syncthreads();

        int kv0 = jt * 64;
        if (kv0 <= q0 + wm + 15) {
            float acc[8][4];
#pragma unroll
            for (int nt = 0; nt < 8; nt++)
#pragma unroll
                for (int i = 0; i < 4; i++) acc[nt][i] = 0.f;
            uint32_t kbase = sK + (uint32_t)(buf * HKVF) * 2;
#pragma unroll
            for (int kk = 0; kk < 4; kk++) {
                uint32_t bf[4][4];
#pragma unroll
                for (int np = 0; np < 4; np++)
                    ldsm4(bf[np], kbase + (uint32_t)((np * 16 + bRow) * HATR + kk * 16 + bColH) * 2);
#pragma unroll
                for (int nt = 0; nt < 8; nt++)
                    mma_h(acc[nt], qf[kk], &bf[nt >> 1][(nt & 1) * 2]);
            }

            int row0 = q0 + wm + g, row1 = row0 + 8;
            if (kv0 + 63 > row0) {
#pragma unroll
                for (int nt = 0; nt < 8; nt++) {
                    int c = kv0 + nt * 8 + 2 * tig;
                    if (c > row0)     acc[nt][0] = NEGINF;
                    if (c + 1 > row0) acc[nt][1] = NEGINF;
                    if (c > row1)     acc[nt][2] = NEGINF;
                    if (c + 1 > row1) acc[nt][3] = NEGINF;
                }
            }

            float tm0 = NEGINF, tm1 = NEGINF;
#pragma unroll
            for (int nt = 0; nt < 8; nt++) {
                tm0 = fmaxf(tm0, fmaxf(acc[nt][0], acc[nt][1]));
                tm1 = fmaxf(tm1, fmaxf(acc[nt][2], acc[nt][3]));
            }
            tm0 = fmaxf(tm0, __shfl_xor_sync(0xffffffffu, tm0, 1));
            tm0 = fmaxf(tm0, __shfl_xor_sync(0xffffffffu, tm0, 2));
            tm1 = fmaxf(tm1, __shfl_xor_sync(0xffffffffu, tm1, 1));
            tm1 = fmaxf(tm1, __shfl_xor_sync(0xffffffffu, tm1, 2));
            float mn0 = fmaxf(mx0, tm0), mn1 = fmaxf(mx1, tm1);
            float cr0 = __expf(mx0 - mn0), cr1 = __expf(mx1 - mn1);
            mx0 = mn0; mx1 = mn1;
            float rs0 = 0.f, rs1 = 0.f;
            __half2* pr0 = (__half2*)(pmem + (wm + g) * HATR + 2 * tig);
            __half2* pr1 = (__half2*)(pmem + (wm + g + 8) * HATR + 2 * tig);
#pragma unroll
            for (int nt = 0; nt < 8; nt++) {
                __half2 p0 = __floats2half2_rn(__expf(acc[nt][0] - mn0), __expf(acc[nt][1] - mn0));
                __half2 p1 = __floats2half2_rn(__expf(acc[nt][2] - mn1), __expf(acc[nt][3] - mn1));
                pr0[nt * 4] = p0;
                pr1[nt * 4] = p1;
                float2 f0 = __half22float2(p0);
                float2 f1 = __half22float2(p1);
                rs0 += f0.x + f0.y;
                rs1 += f1.x + f1.y;
            }
            rs0 += __shfl_xor_sync(0xffffffffu, rs0, 1);
            rs0 += __shfl_xor_sync(0xffffffffu, rs0, 2);
            rs1 += __shfl_xor_sync(0xffffffffu, rs1, 1);
            rs1 += __shfl_xor_sync(0xffffffffu, rs1, 2);
            l0 = l0 * cr0 + rs0;
            l1 = l1 * cr1 + rs1;
#pragma unroll
            for (int nt = 0; nt < 8; nt++) {
                o[nt][0] *= cr0; o[nt][1] *= cr0;
                o[nt][2] *= cr1; o[nt][3] *= cr1;
            }
            __syncwarp();

            uint32_t vbase = sV + (uint32_t)(buf * HKVF) * 2;
#pragma unroll
            for (int kk = 0; kk < 4; kk++) {
                uint32_t pf[4], bv[4][4];
                ldsm4(pf, sP + (uint32_t)(aRowP * HATR + kk * 16 + aColP) * 2);
#pragma unroll
                for (int np = 0; np < 4; np++)
                    ldsm4(bv[np], vbase + (uint32_t)((np * 16 + bRow) * HATR + kk * 16 + bColH) * 2);
#pragma unroll
                for (int nt = 0; nt < 8; nt++)
                    mma_h(o[nt], pf, &bv[nt >> 1][(nt & 1) * 2]);
            }
        }
        __syncthreads();
    }

    float inv0 = 1.f / l0, inv1 = 1.f / l1;
    int r0 = q0 + wm + g;
    __half* o0 = out + (size_t)(b * TT + r0) * DD + h * DHH + 2 * tig;
    __half* o1 = o0 + (size_t)8 * DD;
#pragma unroll
    for (int nt = 0; nt < 8; nt++) {
        *(__half2*)(o0 + nt * 8) = __floats2half2_rn(o[nt][0] * inv0, o[nt][1] * inv0);
        *(__half2*)(o1 + nt * 8) = __floats2half2_rn(o[nt][2] * inv1, o[nt][3] * inv1);
    }
}

// ---------------- silu(gate) * up: gu f16 [M,8192] -> t1 f16 [M,4096] -----------
__global__ void silu_mul_kernel(const __half* __restrict__ gu, __half* __restrict__ t1) {
    int idx = blockIdx.x * 256 + threadIdx.x;
    int m  = idx >> 11;
    int j2 = idx & 2047;
    const __half2* rowp = (const __half2*)(gu + (size_t)m * D8);
    float2 a = __half22float2(rowp[j2]);
    float2 u = __half22float2(rowp[j2 + 2048]);
    a.x = a.x / (1.f + __expf(-a.x)) * u.x;
    a.y = a.y / (1.f + __expf(-a.y)) * u.y;
    ((__half2*)t1)[idx] = __floats2half2_rn(a.x, a.y);
}

// ---------------- launch --------------------------------------------------------
extern "C" void kernel_launch(void* const* d_in, const int* in_sizes, int n_in,
                              void* d_out, int out_size) {
    const float* x       = (const float*)d_in[0];
    const float* w_norm1 = (const float*)d_in[1];
    const float* w_qkv   = (const float*)d_in[2];
    const float* w_proj  = (const float*)d_in[3];
    const float* w_norm2 = (const float*)d_in[4];
    const float* w_gate  = (const float*)d_in[5];
    const float* w_up    = (const float*)d_in[6];
    const float* w_down  = (const float*)d_in[7];

    float* xo = (float*)d_out;
    float* kc = xo + (size_t)MT * DD;
    float* vc = kc + (size_t)BB * HH * TT * DHH;

    __half *h, *att, *gu, *t1, *wh, *ktp, *vtp;
    float *qkv;
    cudaGetSymbolAddress((void**)&h,   g_h);
    cudaGetSymbolAddress((void**)&qkv, g_qkv);
    cudaGetSymbolAddress((void**)&att, g_att);
    cudaGetSymbolAddress((void**)&gu,  g_gu);
    cudaGetSymbolAddress((void**)&t1,  g_t1);
    cudaGetSymbolAddress((void**)&wh,  g_wh);
    cudaGetSymbolAddress((void**)&ktp, g_kt);
    cudaGetSymbolAddress((void**)&vtp, g_vt);

    __half* wh_qkv  = wh;
    __half* wh_proj = wh + (size_t)3 * 1024 * 1024;
    __half* wh_gu   = wh + (size_t)4 * 1024 * 1024;
    __half* wh_down = wh + (size_t)12 * 1024 * 1024;

    cudaFuncSetAttribute(gemm_h<0,0>, cudaFuncAttributeMaxDynamicSharedMemorySize, GEMMH_SMEM);
    cudaFuncSetAttribute(gemm_h<1,0>, cudaFuncAttributeMaxDynamicSharedMemorySize, GEMMH_SMEM);
    cudaFuncSetAttribute(gemm_h<0,1>, cudaFuncAttributeMaxDynamicSharedMemorySize, GEMMH_SMEM);
    cudaFuncSetAttribute(attn_mma,    cudaFuncAttributeMaxDynamicSharedMemorySize, ATTH_SMEM);

    // 0. convert all weights to f16 in one launch (gate/up stacked in g_wh layout)
    cvt_all<<<(16 * 1024 * 1024 / 4) / 256, 256>>>(w_qkv, w_proj, w_gate, w_up, w_down, wh);

    // 1. h = f16(rmsnorm(x) * w1)
    rmsnorm_kernel<<<MT, 256>>>(x, w_norm1, h);
    // 2. qkv = h @ w_qkv^T  (fp32 out)
    gemm_h<0,0><<<dim3(D3 / 256, MT / 128), 512, GEMMH_SMEM>>>(h, wh_qkv, qkv, nullptr, MT, D3, DD);
    // 3. caches (fp32 exact) + f16 K + f16 V^T
    split_kv_kernel<<<dim3(TT / 64, BB * HH), 256>>>(qkv, kc, vc, ktp, vtp);
    // 4. f16 tensor-core causal flash attention -> att (f16)
    attn_mma<<<dim3(TT / 128, BB * HH), 256, ATTH_SMEM>>>(qkv, ktp, vtp, att);
    // 5. x = x + att @ w_proj^T
    gemm_h<1,0><<<dim3(DD / 256, MT / 128), 512, GEMMH_SMEM>>>(att, wh_proj, xo, x, MT, DD, DD);
    // 6. h = f16(rmsnorm(x) * w2)
    rmsnorm_kernel<<<MT, 256>>>(xo, w_norm2, h);
    // 7. gate|up combined (f16 out)
    gemm_h<0,1><<<dim3(D8 / 256, MT / 128), 512, GEMMH_SMEM>>>(h, wh_gu, gu, nullptr, MT, D8, DD);
    // 8. t1 = f16(silu(gate) * up)
    silu_mul_kernel<<<((size_t)MT * D4 / 2) / 256, 256>>>(gu, t1);
    // 9. x += t1 @ w_down^T
    gemm_h<1,0><<<dim3(DD / 256, MT / 128), 512, GEMMH_SMEM>>>(t1, wh_down, xo, xo, MT, DD, D4);
}

// round 8
// speedup vs baseline: 11.3333x; 1.0620x over previous
#include <cuda_runtime.h>
#include <cuda_fp16.h>
#include <math.h>
#include <stdint.h>

#define BB   2
#define TT   2048
#define DD   1024
#define HH   16
#define DHH  64
#define MT   4096            // B*T
#define D3   3072            // 3*D
#define D4   4096            // 4*D
#define D8   8192            // gate+up stacked

// ---------------- scratch (static device arrays; no allocation) ----------------
__device__ __half g_h[MT * DD];                      // rmsnorm output (f16)
__device__ __half g_qh[MT * DD];                     // q, f16, pre-scaled by 1/8
__device__ __half g_att[MT * DD];                    // attention out (f16)
__device__ __half g_t1[(size_t)MT * D4];             // silu(gate)*up (f16)
__device__ __half g_wh[16 * 1024 * 1024];            // converted weights (f16)
__device__ __half g_kt[(size_t)BB * HH * TT * DHH];  // f16 K   [bh][t][dh]
__device__ __half g_vt[(size_t)BB * HH * TT * DHH];  // f16 V^T [bh][dh][t]

// ---------------- helpers -------------------------------------------------------
__device__ __forceinline__ void mma_h(float* c, const uint32_t* a, const uint32_t* b) {
    asm volatile(
        "mma.sync.aligned.m16n8k16.row.col.f32.f16.f16.f32 "
        "{%0,%1,%2,%3}, {%4,%5,%6,%7}, {%8,%9}, {%0,%1,%2,%3};\n"
        : "+f"(c[0]), "+f"(c[1]), "+f"(c[2]), "+f"(c[3])
        : "r"(a[0]), "r"(a[1]), "r"(a[2]), "r"(a[3]), "r"(b[0]), "r"(b[1]));
}
__device__ __forceinline__ void ldsm4(uint32_t* r, uint32_t addr) {
    asm volatile("ldmatrix.sync.aligned.m8n8.x4.shared.b16 {%0,%1,%2,%3}, [%4];"
                 : "=r"(r[0]), "=r"(r[1]), "=r"(r[2]), "=r"(r[3]) : "r"(addr));
}
__device__ __forceinline__ void cpa16(uint32_t dst, const void* src) {
    asm volatile("cp.async.cg.shared.global [%0], [%1], 16;" :: "r"(dst), "l"(src));
}
__device__ __forceinline__ void cp_commit() { asm volatile("cp.async.commit_group;"); }
template <int N>
__device__ __forceinline__ void cp_wait() { asm volatile("cp.async.wait_group %0;" :: "n"(N)); }
__device__ __forceinline__ uint32_t h2u(__half2 h) { return *reinterpret_cast<uint32_t*>(&h); }

// ---------------- fused weight convert ------------------------------------------
// dst layout (halves): [0,3M) qkv | [3M,4M) proj | [4M,12M) gate/up INTERLEAVED
// (row chunk c of 256: rows 0-127 = gate[c*128..], 128-255 = up[c*128..]) | [12M,16M) down
__global__ void cvt_all(const float* __restrict__ wqkv, const float* __restrict__ wproj,
                        const float* __restrict__ wgate, const float* __restrict__ wup,
                        const float* __restrict__ wdown, __half* __restrict__ dst) {
    int idx = blockIdx.x * 256 + threadIdx.x;            // float4 index, 0..4M-1
    float4 v;
    int d;
    if (idx < (3 << 18)) {                               // qkv
        v = ((const float4*)wqkv)[idx];
        d = idx;
    } else if (idx < (4 << 18)) {                        // proj
        v = ((const float4*)wproj)[idx - (3 << 18)];
        d = idx;
    } else if (idx < (8 << 18)) {                        // gate (interleave)
        int i = idx - (4 << 18);
        v = ((const float4*)wgate)[i];
        int j = i >> 8, c4 = i & 255;
        d = (1 << 20) + ((((j >> 7) << 8) + (j & 127)) << 8) + c4;
    } else if (idx < (12 << 18)) {                       // up (interleave)
        int i = idx - (8 << 18);
        v = ((const float4*)wup)[i];
        int j = i >> 8, c4 = i & 255;
        d = (1 << 20) + ((((j >> 7) << 8) + 128 + (j & 127)) << 8) + c4;
    } else {                                             // down
        v = ((const float4*)wdown)[idx - (12 << 18)];
        d = idx;
    }
    __half2 a = __floats2half2_rn(v.x, v.y);
    __half2 b = __floats2half2_rn(v.z, v.w);
    ((uint2*)dst)[d] = make_uint2(h2u(a), h2u(b));
}

// ---------------- RMSNorm (f16 output) ------------------------------------------
__global__ void rmsnorm_kernel(const float* __restrict__ x,
                               const float* __restrict__ w,
                               __half* __restrict__ out) {
    int row = blockIdx.x;
    int t   = threadIdx.x;
    float4 xv = ((const float4*)(x + (size_t)row * DD))[t];
    float s = xv.x * xv.x + xv.y * xv.y + xv.z * xv.z + xv.w * xv.w;
#pragma unroll
    for (int o = 16; o; o >>= 1) s += __shfl_xor_sync(0xffffffffu, s, o);
    __shared__ float red[8];
    __shared__ float rs;
    if ((t & 31) == 0) red[t >> 5] = s;
    __syncthreads();
    if (t == 0) {
        float tot = 0.f;
#pragma unroll
        for (int i = 0; i < 8; i++) tot += red[i];
        rs = rsqrtf(tot * (1.0f / DD) + 1e-6f);
    }
    __syncthreads();
    float r = rs;
    float4 wv = ((const float4*)w)[t];
    __half2 a = __floats2half2_rn(xv.x * r * wv.x, xv.y * r * wv.y);
    __half2 b = __floats2half2_rn(xv.z * r * wv.z, xv.w * r * wv.w);
    ((uint2*)(out + (size_t)row * DD))[t] = make_uint2(h2u(a), h2u(b));
}

// ---------------- f16 tensor-core NT GEMM, 128(M) x 256(N) tiles ----------------
// MODE 0: fp32 C (+R residual).  MODE 2: qkv scatter (q f16 scaled / caches / kt / vt).
// MODE 3: fused silu(gate)*up -> t1 f16 (gate/up interleaved weights).
#define HST 40
#define HSTG 4
#define G_AH (128 * HST)
#define G_BH (256 * HST)
#define GEMMH_SMEM (HSTG * (G_AH + G_BH) * 2)   // 122880 B

template <int MODE>
__global__ void __launch_bounds__(512, 1)
gemm_h(const __half* __restrict__ A, const __half* __restrict__ B,
       float* __restrict__ C, const float* __restrict__ R,
       __half* __restrict__ qh, float* __restrict__ kc, float* __restrict__ vc,
       __half* __restrict__ kt, __half* __restrict__ vt, __half* __restrict__ t1,
       int M, int N, int K) {
    extern __shared__ __half smg[];
    uint32_t sA = (uint32_t)__cvta_generic_to_shared(smg);
    uint32_t sB = sA + HSTG * G_AH * 2;

    int tid  = threadIdx.x;
    int warp = tid >> 5, lane = tid & 31;
    int g = lane >> 2, tig = lane & 3;
    int wm = (warp >> 2) * 32;
    int wn = (warp & 3) * 64;
    int bm = blockIdx.y * 128, bn = blockIdx.x * 256;

    int alr = tid >> 2;
    int alk = (tid & 3) * 8;
    const __half* Ag = A + (size_t)(bm + alr) * K + alk;
    uint32_t dA = sA + (uint32_t)(alr * HST + alk) * 2;
    int blr = tid >> 1;
    int blk = (tid & 1) * 16;
    const __half* Bg = B + (size_t)(bn + blr) * K + blk;
    uint32_t dB = sB + (uint32_t)(blr * HST + blk) * 2;

    int aRow = wm + (lane & 15);
    int aColH = (lane >> 4) * 8;
    int bRow = (lane & 7) + ((lane >> 4) & 1) * 8;
    int bColH = ((lane >> 3) & 1) * 8;

    float acc[2][8][4];
#pragma unroll
    for (int i = 0; i < 2; i++)
#pragma unroll
        for (int j = 0; j < 8; j++)
#pragma unroll
            for (int q = 0; q < 4; q++) acc[i][j][q] = 0.f;

#pragma unroll
    for (int s = 0; s < HSTG - 1; s++) {
        uint32_t ao = (uint32_t)(s * G_AH * 2);
        uint32_t bo = (uint32_t)(s * G_BH * 2);
        int ko = s * 32;
        cpa16(dA + ao,      Ag + ko);
        cpa16(dB + bo,      Bg + ko);
        cpa16(dB + bo + 16, Bg + ko + 8);
        cp_commit();
    }

    int rd = 0, wr = HSTG - 1;
    int iters = K >> 5;
    cp_wait<HSTG - 2>();
    __syncthreads();

    for (int it = 0; it < iters; it++) {
        uint32_t stA = sA + (uint32_t)(rd * G_AH * 2);
        uint32_t stB = sB + (uint32_t)(rd * G_BH * 2);
#pragma unroll
        for (int kk = 0; kk < 2; kk++) {
            uint32_t af[2][4], bf[4][4];
#pragma unroll
            for (int mt = 0; mt < 2; mt++)
                ldsm4(af[mt], stA + (uint32_t)((aRow + mt * 16) * HST + kk * 16 + aColH) * 2);
#pragma unroll
            for (int np = 0; np < 4; np++)
                ldsm4(bf[np], stB + (uint32_t)((wn + np * 16 + bRow) * HST + kk * 16 + bColH) * 2);
#pragma unroll
            for (int mt = 0; mt < 2; mt++)
#pragma unroll
                for (int nt = 0; nt < 8; nt++)
                    mma_h(acc[mt][nt], af[mt], &bf[nt >> 1][(nt & 1) * 2]);
        }
        int nk = (it + HSTG - 1) * 32;
        if (nk < K) {
            uint32_t ao = (uint32_t)(wr * G_AH * 2);
            uint32_t bo = (uint32_t)(wr * G_BH * 2);
            cpa16(dA + ao,      Ag + nk);
            cpa16(dB + bo,      Bg + nk);
            cpa16(dB + bo + 16, Bg + nk + 8);
        }
        cp_commit();
        wr = rd;
        rd = (rd + 1) & (HSTG - 1);
        cp_wait<HSTG - 2>();
        __syncthreads();
    }

    if (MODE == 0) {
#pragma unroll
        for (int mt = 0; mt < 2; mt++) {
#pragma unroll
            for (int nt = 0; nt < 8; nt++) {
                int r0 = bm + wm + mt * 16 + g;
                int c0 = bn + wn + nt * 8 + 2 * tig;
                size_t o0 = (size_t)r0 * N + c0;
                size_t o1 = (size_t)(r0 + 8) * N + c0;
                float2 v0 = make_float2(acc[mt][nt][0], acc[mt][nt][1]);
                float2 v1 = make_float2(acc[mt][nt][2], acc[mt][nt][3]);
                float2 r4 = *(const float2*)(R + o0);
                v0.x += r4.x; v0.y += r4.y;
                float2 r5 = *(const float2*)(R + o1);
                v1.x += r5.x; v1.y += r5.y;
                *(float2*)(C + o0) = v0;
                *(float2*)(C + o1) = v1;
            }
        }
    } else if (MODE == 2) {
        int kind = bn >> 10;                    // 0=q 1=k 2=v
#pragma unroll
        for (int mt = 0; mt < 2; mt++) {
#pragma unroll
            for (int nt = 0; nt < 8; nt++) {
                int m0 = bm + wm + mt * 16 + g;
                int c0 = bn + wn + nt * 8 + 2 * tig;
                float2 v0 = make_float2(acc[mt][nt][0], acc[mt][nt][1]);
                float2 v1 = make_float2(acc[mt][nt][2], acc[mt][nt][3]);
                if (kind == 0) {
                    *(__half2*)(qh + (size_t)m0 * DD + c0) =
                        __floats2half2_rn(v0.x * 0.125f, v0.y * 0.125f);
                    *(__half2*)(qh + (size_t)(m0 + 8) * DD + c0) =
                        __floats2half2_rn(v1.x * 0.125f, v1.y * 0.125f);
                } else {
                    int cc = c0 & 1023;
                    int hh = cc >> 6, dh = cc & 63;
                    int b0 = m0 >> 11, t0 = m0 & 2047;
                    int bh = b0 * HH + hh;
                    size_t ix0 = ((size_t)bh * TT + t0) * DHH + dh;
                    size_t ix1 = ((size_t)bh * TT + t0 + 8) * DHH + dh;
                    if (kind == 1) {
                        *(float2*)(kc + ix0) = v0;
                        *(float2*)(kc + ix1) = v1;
                        *(__half2*)(kt + ix0) = __floats2half2_rn(v0.x, v0.y);
                        *(__half2*)(kt + ix1) = __floats2half2_rn(v1.x, v1.y);
                    } else {
                        *(float2*)(vc + ix0) = v0;
                        *(float2*)(vc + ix1) = v1;
                        __half* vb0 = vt + (size_t)(bh * DHH + dh) * TT + t0;
                        __half* vb1 = vt + (size_t)(bh * DHH + dh + 1) * TT + t0;
                        vb0[0] = __float2half_rn(v0.x);
                        vb1[0] = __float2half_rn(v0.y);
                        vb0[8] = __float2half_rn(v1.x);
                        vb1[8] = __float2half_rn(v1.y);
                    }
                }
            }
        }
    } else {   // MODE 3: silu fuse; cols [0,128)=gate chunk, [128,256)=up chunk
        __syncthreads();                        // cp.async data consumed; reuse smem
        float* ex = (float*)smg;                // [128][132]
        if (wn >= 128) {
#pragma unroll
            for (int mt = 0; mt < 2; mt++)
#pragma unroll
                for (int nt = 0; nt < 8; nt++) {
                    int lr0 = wm + mt * 16 + g;
                    int cl = wn - 128 + nt * 8 + 2 * tig;
                    *(float2*)(ex + lr0 * 132 + cl) = make_float2(acc[mt][nt][0], acc[mt][nt][1]);
                    *(float2*)(ex + (lr0 + 8) * 132 + cl) = make_float2(acc[mt][nt][2], acc[mt][nt][3]);
                }
        }
        __syncthreads();
        if (wn < 128) {
            int tcol = (bn >> 1);               // output column base = chunk*128
#pragma unroll
            for (int mt = 0; mt < 2; mt++)
#pragma unroll
                for (int nt = 0; nt < 8; nt++) {
                    int lr0 = wm + mt * 16 + g;
                    int cl = wn + nt * 8 + 2 * tig;
                    float2 u0 = *(const float2*)(ex + lr0 * 132 + cl);
                    float2 u1 = *(const float2*)(ex + (lr0 + 8) * 132 + cl);
                    float g0 = acc[mt][nt][0], g1 = acc[mt][nt][1];
                    float g2 = acc[mt][nt][2], g3 = acc[mt][nt][3];
                    g0 = g0 / (1.f + __expf(-g0)) * u0.x;
                    g1 = g1 / (1.f + __expf(-g1)) * u0.y;
                    g2 = g2 / (1.f + __expf(-g2)) * u1.x;
                    g3 = g3 / (1.f + __expf(-g3)) * u1.y;
                    size_t o0 = (size_t)(bm + lr0) * D4 + tcol + cl;
                    size_t o1 = (size_t)(bm + lr0 + 8) * D4 + tcol + cl;
                    *(__half2*)(t1 + o0) = __floats2half2_rn(g0, g1);
                    *(__half2*)(t1 + o1) = __floats2half2_rn(g2, g3);
                }
        }
    }
}

// ---------------- f16 tensor-core flash attention --------------------------------
#define HATR 72
#define HKVF (64 * HATR)
#define ATTH_SMEM ((4 * HKVF + 128 * HATR) * 2)
#define NEGINF __int_as_float(0xff800000)

__global__ void __launch_bounds__(256, 2)
attn_mma(const __half* __restrict__ qh, const __half* __restrict__ kt,
         const __half* __restrict__ vt, __half* __restrict__ out) {
    extern __shared__ __half smh[];
    uint32_t sbase = (uint32_t)__cvta_generic_to_shared(smh);
    const uint32_t sK = sbase;
    const uint32_t sV = sbase + 2 * HKVF * 2;
    const uint32_t sP = sbase + 4 * HKVF * 2;
    __half* pmem = smh + 4 * HKVF;

    int qt = (int)(gridDim.x - 1) - (int)blockIdx.x;
    int bh = blockIdx.y;
    int b = bh >> 4, h = bh & 15;
    int q0 = qt * 128;
    int tid = threadIdx.x;
    int warp = tid >> 5, lane = tid & 31;
    int g = lane >> 2, tig = lane & 3;
    int wm = warp * 16;

    const __half* ktb = kt + (size_t)bh * TT * DHH;
    const __half* vtb = vt + (size_t)bh * DHH * TT;

    auto load_tile = [&](int jt, int s) {
        int kv = jt * 64;
        int r = tid >> 2;
        int cbh = (tid & 3) * 16;
        const __half* ksrc = ktb + (size_t)(kv + r) * DHH + cbh;
        const __half* vsrc = vtb + (size_t)r * TT + kv + cbh;
        uint32_t kd = sK + (uint32_t)(s * HKVF + r * HATR + cbh) * 2;
        uint32_t vd = sV + (uint32_t)(s * HKVF + r * HATR + cbh) * 2;
        cpa16(kd,      ksrc);
        cpa16(kd + 16, ksrc + 8);
        cpa16(vd,      vsrc);
        cpa16(vd + 16, vsrc + 8);
    };

    // stage Q (f16, pre-scaled) via cp.async — group 0
    {
        int row = tid >> 1;
        int part = (tid & 1) * 32;
        const __half* src = qh + (size_t)(b * TT + q0 + row) * DD + h * DHH + part;
        uint32_t dst = sP + (uint32_t)(row * HATR + part) * 2;
#pragma unroll
        for (int i = 0; i < 4; i++) cpa16(dst + i * 16, src + i * 8);
        cp_commit();
    }
    load_tile(0, 0);       // group 1
    cp_commit();

    cp_wait<1>();          // q ready (tile0 may still be in flight)
    __syncthreads();
    uint32_t qf[4][4];
    {
        int aRow = wm + (lane & 15);
        int aColH = (lane >> 4) * 8;
#pragma unroll
        for (int kk = 0; kk < 4; kk++)
            ldsm4(qf[kk], sP + (uint32_t)(aRow * HATR + kk * 16 + aColH) * 2);
    }
    __syncthreads();

    float o[8][4];
#pragma unroll
    for (int nt = 0; nt < 8; nt++)
#pragma unroll
        for (int i = 0; i < 4; i++) o[nt][i] = 0.f;
    float mx0 = -1e30f, mx1 = -1e30f, l0 = 0.f, l1 = 0.f;

    int nT = 2 * qt + 2;
    int bRow = (lane & 7) + ((lane >> 4) & 1) * 8;
    int bColH = ((lane >> 3) & 1) * 8;
    int aRowP = wm + (lane & 15);
    int aColP = (lane >> 4) * 8;

    for (int jt = 0; jt < nT; jt++) {
        int buf = jt & 1;
        if (jt + 1 < nT) { load_tile(jt + 1, buf ^ 1); cp_commit(); cp_wait<1>(); }
        else             { cp_commit(); cp_wait<0>(); }
        __syncthreads();

        int kv0 = jt * 64;
        if (kv0 <= q0 + wm + 15) {
            float acc[8][4];
#pragma unroll
            for (int nt = 0; nt < 8; nt++)
#pragma unroll
                for (int i = 0; i < 4; i++) acc[nt][i] = 0.f;
            uint32_t kbase = sK + (uint32_t)(buf * HKVF) * 2;
#pragma unroll
            for (int kk = 0; kk < 4; kk++) {
                uint32_t bf[4][4];
#pragma unroll
                for (int np = 0; np < 4; np++)
                    ldsm4(bf[np], kbase + (uint32_t)((np * 16 + bRow) * HATR + kk * 16 + bColH) * 2);
#pragma unroll
                for (int nt = 0; nt < 8; nt++)
                    mma_h(acc[nt], qf[kk], &bf[nt >> 1][(nt & 1) * 2]);
            }

            int row0 = q0 + wm + g, row1 = row0 + 8;
            if (kv0 + 63 > row0) {
#pragma unroll
                for (int nt = 0; nt < 8; nt++) {
                    int c = kv0 + nt * 8 + 2 * tig;
                    if (c > row0)     acc[nt][0] = NEGINF;
                    if (c + 1 > row0) acc[nt][1] = NEGINF;
                    if (c > row1)     acc[nt][2] = NEGINF;
                    if (c + 1 > row1) acc[nt][3] = NEGINF;
                }
            }

            float tm0 = NEGINF, tm1 = NEGINF;
#pragma unroll
            for (int nt = 0; nt < 8; nt++) {
                tm0 = fmaxf(tm0, fmaxf(acc[nt][0], acc[nt][1]));
                tm1 = fmaxf(tm1, fmaxf(acc[nt][2], acc[nt][3]));
            }
            tm0 = fmaxf(tm0, __shfl_xor_sync(0xffffffffu, tm0, 1));
            tm0 = fmaxf(tm0, __shfl_xor_sync(0xffffffffu, tm0, 2));
            tm1 = fmaxf(tm1, __shfl_xor_sync(0xffffffffu, tm1, 1));
            tm1 = fmaxf(tm1, __shfl_xor_sync(0xffffffffu, tm1, 2));
            float mn0 = fmaxf(mx0, tm0), mn1 = fmaxf(mx1, tm1);
            float cr0 = __expf(mx0 - mn0), cr1 = __expf(mx1 - mn1);
            mx0 = mn0; mx1 = mn1;
            float rs0 = 0.f, rs1 = 0.f;
            __half2* pr0 = (__half2*)(pmem + (wm + g) * HATR + 2 * tig);
            __half2* pr1 = (__half2*)(pmem + (wm + g + 8) * HATR + 2 * tig);
#pragma unroll
            for (int nt = 0; nt < 8; nt++) {
                __half2 p0 = __floats2half2_rn(__expf(acc[nt][0] - mn0), __expf(acc[nt][1] - mn0));
                __half2 p1 = __floats2half2_rn(__expf(acc[nt][2] - mn1), __expf(acc[nt][3] - mn1));
                pr0[nt * 4] = p0;
                pr1[nt * 4] = p1;
                float2 f0 = __half22float2(p0);
                float2 f1 = __half22float2(p1);
                rs0 += f0.x + f0.y;
                rs1 += f1.x + f1.y;
            }
            rs0 += __shfl_xor_sync(0xffffffffu, rs0, 1);
            rs0 += __shfl_xor_sync(0xffffffffu, rs0, 2);
            rs1 += __shfl_xor_sync(0xffffffffu, rs1, 1);
            rs1 += __shfl_xor_sync(0xffffffffu, rs1, 2);
            l0 = l0 * cr0 + rs0;
            l1 = l1 * cr1 + rs1;
#pragma unroll
            for (int nt = 0; nt < 8; nt++) {
                o[nt][0] *= cr0; o[nt][1] *= cr0;
                o[nt][2] *= cr1; o[nt][3] *= cr1;
            }
            __syncwarp();

            uint32_t vbase = sV + (uint32_t)(buf * HKVF) * 2;
#pragma unroll
            for (int kk = 0; kk < 4; kk++) {
                uint32_t pf[4], bv[4][4];
                ldsm4(pf, sP + (uint32_t)(aRowP * HATR + kk * 16 + aColP) * 2);
#pragma unroll
                for (int np = 0; np < 4; np++)
                    ldsm4(bv[np], vbase + (uint32_t)((np * 16 + bRow) * HATR + kk * 16 + bColH) * 2);
#pragma unroll
                for (int nt = 0; nt < 8; nt++)
                    mma_h(o[nt], pf, &bv[nt >> 1][(nt & 1) * 2]);
            }
        }
        __syncthreads();
    }

    float inv0 = 1.f / l0, inv1 = 1.f / l1;
    int r0 = q0 + wm + g;
    __half* o0 = out + (size_t)(b * TT + r0) * DD + h * DHH + 2 * tig;
    __half* o1 = o0 + (size_t)8 * DD;
#pragma unroll
    for (int nt = 0; nt < 8; nt++) {
        *(__half2*)(o0 + nt * 8) = __floats2half2_rn(o[nt][0] * inv0, o[nt][1] * inv0);
        *(__half2*)(o1 + nt * 8) = __floats2half2_rn(o[nt][2] * inv1, o[nt][3] * inv1);
    }
}

// ---------------- launch --------------------------------------------------------
extern "C" void kernel_launch(void* const* d_in, const int* in_sizes, int n_in,
                              void* d_out, int out_size) {
    const float* x       = (const float*)d_in[0];
    const float* w_norm1 = (const float*)d_in[1];
    const float* w_qkv   = (const float*)d_in[2];
    const float* w_proj  = (const float*)d_in[3];
    const float* w_norm2 = (const float*)d_in[4];
    const float* w_gate  = (const float*)d_in[5];
    const float* w_up    = (const float*)d_in[6];
    const float* w_down  = (const float*)d_in[7];

    float* xo = (float*)d_out;
    float* kc = xo + (size_t)MT * DD;
    float* vc = kc + (size_t)BB * HH * TT * DHH;

    __half *h, *qh, *att, *t1, *wh, *ktp, *vtp;
    cudaGetSymbolAddress((void**)&h,   g_h);
    cudaGetSymbolAddress((void**)&qh,  g_qh);
    cudaGetSymbolAddress((void**)&att, g_att);
    cudaGetSymbolAddress((void**)&t1,  g_t1);
    cudaGetSymbolAddress((void**)&wh,  g_wh);
    cudaGetSymbolAddress((void**)&ktp, g_kt);
    cudaGetSymbolAddress((void**)&vtp, g_vt);

    __half* wh_qkv  = wh;
    __half* wh_proj = wh + (size_t)3 * 1024 * 1024;
    __half* wh_gu   = wh + (size_t)4 * 1024 * 1024;
    __half* wh_down = wh + (size_t)12 * 1024 * 1024;

    cudaFuncSetAttribute(gemm_h<0>, cudaFuncAttributeMaxDynamicSharedMemorySize, GEMMH_SMEM);
    cudaFuncSetAttribute(gemm_h<2>, cudaFuncAttributeMaxDynamicSharedMemorySize, GEMMH_SMEM);
    cudaFuncSetAttribute(gemm_h<3>, cudaFuncAttributeMaxDynamicSharedMemorySize, GEMMH_SMEM);
    cudaFuncSetAttribute(attn_mma,  cudaFuncAttributeMaxDynamicSharedMemorySize, ATTH_SMEM);

    // 0. convert all weights (gate/up interleaved)
    cvt_all<<<(16 * 1024 * 1024 / 4) / 256, 256>>>(w_qkv, w_proj, w_gate, w_up, w_down, wh);

    // 1. h = f16(rmsnorm(x) * w1)
    rmsnorm_kernel<<<MT, 256>>>(x, w_norm1, h);
    // 2. qkv GEMM with fused scatter: q->qh (f16, scaled), k/v->caches + kt/vt
    gemm_h<2><<<dim3(D3 / 256, MT / 128), 512, GEMMH_SMEM>>>(
        h, wh_qkv, nullptr, nullptr, qh, kc, vc, ktp, vtp, nullptr, MT, D3, DD);
    // 3. f16 causal flash attention -> att
    attn_mma<<<dim3(TT / 128, BB * HH), 256, ATTH_SMEM>>>(qh, ktp, vtp, att);
    // 4. x = x + att @ w_proj^T
    gemm_h<0><<<dim3(DD / 256, MT / 128), 512, GEMMH_SMEM>>>(
        att, wh_proj, xo, x, nullptr, nullptr, nullptr, nullptr, nullptr, nullptr, MT, DD, DD);
    // 5. h = f16(rmsnorm(x) * w2)
    rmsnorm_kernel<<<MT, 256>>>(xo, w_norm2, h);
    // 6. gate/up GEMM with fused silu -> t1 (f16)
    gemm_h<3><<<dim3(D8 / 256, MT / 128), 512, GEMMH_SMEM>>>(
        h, wh_gu, nullptr, nullptr, nullptr, nullptr, nullptr, nullptr, nullptr, t1, MT, D8, DD);
    // 7. x += t1 @ w_down^T
    gemm_h<0><<<dim3(DD / 256, MT / 128), 512, GEMMH_SMEM>>>(
        t1, wh_down, xo, xo, nullptr, nullptr, nullptr, nullptr, nullptr, nullptr, MT, DD, D4);
}